// round 1
// baseline (speedup 1.0000x reference)
#include <cuda_runtime.h>
#include <math.h>

// ---------------- scratch (device globals; allocation-free) ----------------
// max intermediate: [2,64,512,512] = 33,554,432 floats
__device__ float d_bufA[33554432];
__device__ float d_bufB[33554432];
__device__ float d_compbuf[2 * 3 * 512 * 512];          // 1,572,864
__device__ float d_p1[3 * 2 * 64 * 256 * 256];          // 3 x 8,388,608
__device__ float d_p2[3 * 2 * 128 * 128 * 128];         // 3 x 4,194,304
__device__ float d_p3[3 * 2 * 256 * 64 * 64];           // 3 x 2,097,152
__device__ double d_loss;

// ---------------- helpers ----------------
__device__ __forceinline__ void block_reduce_add(float v, double scale) {
    __shared__ float red[256];
    int t = threadIdx.y * blockDim.x + threadIdx.x;
    red[t] = v;
    __syncthreads();
    for (int s = 128; s > 0; s >>= 1) {
        if (t < s) red[t] += red[t + s];
        __syncthreads();
    }
    if (t == 0) atomicAdd(&d_loss, scale * (double)red[0]);
}

__global__ void k_zero() { d_loss = 0.0; }

__global__ void k_final(float* out) { out[0] = (float)d_loss; }

// ---------------- composite image: icomp = m ? igt : iout ----------------
__global__ void k_comp(const float* __restrict__ igt, const float* __restrict__ iout,
                       const float* __restrict__ mask) {
    const int HW2 = 512 * 512;
    const int n = 2 * 3 * HW2;
    int idx = blockIdx.x * blockDim.x + threadIdx.x;
    if (idx >= n) return;
    int b = idx / (3 * HW2);
    int p = idx % HW2;
    bool m = (mask[b * HW2 + p] != 0.0f);
    d_compbuf[idx] = m ? igt[idx] : iout[idx];
}

// ---------------- l_hole + l_valid ----------------
// l_hole = B * sum|(1-m)*diff| / N ; l_valid = sum|m*diff| / N ; N = 3*H*W*B
__global__ void k_holevalid(const float* __restrict__ igt, const float* __restrict__ iout,
                            const float* __restrict__ mask) {
    const int HW2 = 512 * 512;
    const int n = 2 * 3 * HW2;
    float s = 0.f;
    for (int idx = blockIdx.x * blockDim.x + threadIdx.x; idx < n;
         idx += gridDim.x * blockDim.x) {
        int b = idx / (3 * HW2);
        int p = idx % HW2;
        bool m = (mask[b * HW2 + p] != 0.0f);
        float d = fabsf(iout[idx] - igt[idx]);
        s += d * (m ? 1.0f : 2.0f);   // valid weight 1, hole weight B=2
    }
    block_reduce_add(s, 1.0 / (3.0 * 512.0 * 512.0 * 2.0));
}

// ---------------- perceptual L1: (|out-gt| + |comp-gt|) * scale ----------------
__global__ void k_perc(const float* __restrict__ po, const float* __restrict__ pg,
                       const float* __restrict__ pc, int n, double scale) {
    float s = 0.f;
    for (int i = blockIdx.x * blockDim.x + threadIdx.x; i < n;
         i += gridDim.x * blockDim.x) {
        float g = pg[i];
        s += fabsf(po[i] - g) + fabsf(pc[i] - g);
    }
    block_reduce_add(s, scale);
}

// ---------------- 2x2 max pool ----------------
__global__ void k_pool(const float* __restrict__ in, float* __restrict__ out,
                       int BC, int Hout) {
    int n = BC * Hout * Hout;
    int idx = blockIdx.x * blockDim.x + threadIdx.x;
    if (idx >= n) return;
    int c = idx / (Hout * Hout);
    int r = idx % (Hout * Hout);
    int y = r / Hout, x = r % Hout;
    int Hin = Hout * 2;
    const float* p = in + ((size_t)c * Hin + 2 * y) * Hin + 2 * x;
    float v0 = fmaxf(p[0], p[1]);
    float v1 = fmaxf(p[Hin], p[Hin + 1]);
    out[idx] = fmaxf(v0, v1);
}

// ---------------- direct 3x3 conv + bias + relu (SAME padding) ----------------
// Block: 16x16 threads; tile 16 wide x 32 tall (2 rows/thread); 4 output channels/block.
__global__ __launch_bounds__(256) void k_conv(
    const float* __restrict__ in, float* __restrict__ out,
    const float* __restrict__ wt, const float* __restrict__ bs,
    int Cin, int Cout, int HW) {
    __shared__ float sIn[34][18];
    __shared__ float sW[9216];   // up to Cin=256 * 4 couts * 9
    __shared__ float sB[4];

    const int tx = threadIdx.x, ty = threadIdx.y;
    const int tid = ty * 16 + tx;
    const int cb = Cout >> 2;
    const int b = blockIdx.z / cb;
    const int c0 = (blockIdx.z % cb) * 4;
    const int x0 = blockIdx.x * 16, y0 = blockIdx.y * 32;

    const int nW = Cin * 36;
    for (int i = tid; i < nW; i += 256) {
        int f = i / (Cin * 9);
        int r = i - f * Cin * 9;
        sW[i] = wt[(size_t)(c0 + f) * Cin * 9 + r];
    }
    if (tid < 4) sB[tid] = bs[c0 + tid];

    float acc0[4] = {0.f, 0.f, 0.f, 0.f};
    float acc1[4] = {0.f, 0.f, 0.f, 0.f};
    const float* inB = in + (size_t)b * Cin * HW * HW;

    for (int cin = 0; cin < Cin; ++cin) {
        __syncthreads();
        const float* ip = inB + (size_t)cin * HW * HW;
        for (int i = tid; i < 34 * 18; i += 256) {
            int py = i / 18, px = i - py * 18;
            int gy = y0 - 1 + py, gx = x0 - 1 + px;
            float v = 0.f;
            if (gy >= 0 && gy < HW && gx >= 0 && gx < HW)
                v = ip[(size_t)gy * HW + gx];
            sIn[py][px] = v;
        }
        __syncthreads();

        float a00 = sIn[ty][tx],      a01 = sIn[ty][tx + 1],      a02 = sIn[ty][tx + 2];
        float a10 = sIn[ty + 1][tx],  a11 = sIn[ty + 1][tx + 1],  a12 = sIn[ty + 1][tx + 2];
        float a20 = sIn[ty + 2][tx],  a21 = sIn[ty + 2][tx + 1],  a22 = sIn[ty + 2][tx + 2];
        float b00 = sIn[ty + 16][tx], b01 = sIn[ty + 16][tx + 1], b02 = sIn[ty + 16][tx + 2];
        float b10 = sIn[ty + 17][tx], b11 = sIn[ty + 17][tx + 1], b12 = sIn[ty + 17][tx + 2];
        float b20 = sIn[ty + 18][tx], b21 = sIn[ty + 18][tx + 1], b22 = sIn[ty + 18][tx + 2];

        const float* wbase = sW + cin * 9;
        #pragma unroll
        for (int f = 0; f < 4; ++f) {
            const float* wf = wbase + f * Cin * 9;
            float w0 = wf[0], w1 = wf[1], w2 = wf[2];
            float w3 = wf[3], w4 = wf[4], w5 = wf[5];
            float w6 = wf[6], w7 = wf[7], w8 = wf[8];
            acc0[f] += a00 * w0 + a01 * w1 + a02 * w2
                     + a10 * w3 + a11 * w4 + a12 * w5
                     + a20 * w6 + a21 * w7 + a22 * w8;
            acc1[f] += b00 * w0 + b01 * w1 + b02 * w2
                     + b10 * w3 + b11 * w4 + b12 * w5
                     + b20 * w6 + b21 * w7 + b22 * w8;
        }
    }

    const size_t HW2 = (size_t)HW * HW;
    #pragma unroll
    for (int f = 0; f < 4; ++f) {
        float v0 = fmaxf(acc0[f] + sB[f], 0.f);
        float v1 = fmaxf(acc1[f] + sB[f], 0.f);
        size_t o = (size_t)(b * Cout + c0 + f) * HW2 + (size_t)(y0 + ty) * HW + (x0 + tx);
        out[o] = v0;
        out[o + (size_t)16 * HW] = v1;
    }
}

// ---------------- fused style Gram kernel ----------------
// Per (b,c): G[w,v] = sum_h a[h,w]*a[h,v].  Computes Gram tiles for gt, out, comp
// simultaneously, accumulates sum |G_out - G_gt| + |G_comp - G_gt| with symmetry
// (only upper-triangular tile pairs; off-diagonal weighted x2).
__global__ __launch_bounds__(256) void k_gram(
    const float* __restrict__ g, const float* __restrict__ a0,
    const float* __restrict__ a1, int Wd, double scale) {
    const int jt = blockIdx.x, it = blockIdx.y;
    if (jt < it) return;

    __shared__ float sw[3][16][64];
    __shared__ float sv[3][16][64];
    const int tx = threadIdx.x, ty = threadIdx.y;
    const int tid = ty * 16 + tx;
    const size_t base = (size_t)blockIdx.z * Wd * Wd;
    const float* mats[3] = {g, a0, a1};

    float aG[16], aO[16], aC[16];
    #pragma unroll
    for (int i = 0; i < 16; ++i) { aG[i] = 0.f; aO[i] = 0.f; aC[i] = 0.f; }

    const int w0 = it * 64, v0 = jt * 64;
    for (int kb = 0; kb < Wd; kb += 16) {
        __syncthreads();
        for (int m = 0; m < 3; ++m) {
            const float* src = mats[m] + base + (size_t)kb * Wd;
            for (int i = tid; i < 1024; i += 256) {
                int kr = i >> 6, col = i & 63;
                sw[m][kr][col] = src[(size_t)kr * Wd + w0 + col];
                sv[m][kr][col] = src[(size_t)kr * Wd + v0 + col];
            }
        }
        __syncthreads();
        for (int k = 0; k < 16; ++k) {
            float gw[4], ow[4], cw[4], gv[4], ov[4], cv[4];
            #pragma unroll
            for (int r = 0; r < 4; ++r) {
                gw[r] = sw[0][k][ty + 16 * r];
                ow[r] = sw[1][k][ty + 16 * r];
                cw[r] = sw[2][k][ty + 16 * r];
                gv[r] = sv[0][k][tx + 16 * r];
                ov[r] = sv[1][k][tx + 16 * r];
                cv[r] = sv[2][k][tx + 16 * r];
            }
            #pragma unroll
            for (int r = 0; r < 4; ++r)
                #pragma unroll
                for (int s = 0; s < 4; ++s) {
                    aG[r * 4 + s] += gw[r] * gv[s];
                    aO[r * 4 + s] += ow[r] * ov[s];
                    aC[r * 4 + s] += cw[r] * cv[s];
                }
        }
    }

    float sum = 0.f;
    #pragma unroll
    for (int r = 0; r < 4; ++r)
        #pragma unroll
        for (int s = 0; s < 4; ++s) {
            int w = w0 + ty + 16 * r;
            int v = v0 + tx + 16 * s;
            float wgt = (jt > it) ? 2.f : (v > w ? 2.f : (v == w ? 1.f : 0.f));
            float gg = aG[r * 4 + s];
            sum += wgt * (fabsf(aO[r * 4 + s] - gg) + fabsf(aC[r * 4 + s] - gg));
        }
    block_reduce_add(sum, scale);
}

// ---------------- host orchestration ----------------
static void conv_launch(const float* in, float* out, const float* w, const float* b,
                        int Cin, int Cout, int HW) {
    dim3 grid(HW / 16, HW / 32, 2 * (Cout / 4));
    dim3 blk(16, 16);
    k_conv<<<grid, blk>>>(in, out, w, b, Cin, Cout, HW);
}

static void pool_launch(const float* in, float* out, int BC, int Hout) {
    int n = BC * Hout * Hout;
    k_pool<<<(n + 255) / 256, 256>>>(in, out, BC, Hout);
}

extern "C" void kernel_launch(void* const* d_in, const int* in_sizes, int n_in,
                              void* d_out, int out_size) {
    const float* igt  = (const float*)d_in[0];
    const float* iout = (const float*)d_in[1];
    const float* mask = (const float*)d_in[2];
    const float* W[7];
    const float* Bi[7];
    for (int i = 0; i < 7; ++i) {
        W[i]  = (const float*)d_in[3 + 2 * i];
        Bi[i] = (const float*)d_in[4 + 2 * i];
    }

    float *bufA, *bufB, *comp, *p1, *p2, *p3;
    cudaGetSymbolAddress((void**)&bufA, d_bufA);
    cudaGetSymbolAddress((void**)&bufB, d_bufB);
    cudaGetSymbolAddress((void**)&comp, d_compbuf);
    cudaGetSymbolAddress((void**)&p1, d_p1);
    cudaGetSymbolAddress((void**)&p2, d_p2);
    cudaGetSymbolAddress((void**)&p3, d_p3);

    const size_t s1 = 2ull * 64 * 256 * 256;   // 8,388,608
    const size_t s2 = 2ull * 128 * 128 * 128;  // 4,194,304
    const size_t s3 = 2ull * 256 * 64 * 64;    // 2,097,152

    k_zero<<<1, 1>>>();

    const int nC = 2 * 3 * 512 * 512;
    k_comp<<<(nC + 255) / 256, 256>>>(igt, iout, mask);
    k_holevalid<<<1024, 256>>>(igt, iout, mask);

    // image index: 0 = iout, 1 = igt, 2 = icomp
    for (int img = 0; img < 3; ++img) {
        const float* src = (img == 0) ? iout : (img == 1) ? igt : comp;
        conv_launch(src, bufA, W[0], Bi[0], 3, 64, 512);
        conv_launch(bufA, bufB, W[1], Bi[1], 64, 64, 512);
        pool_launch(bufB, p1 + img * s1, 2 * 64, 256);
        conv_launch(p1 + img * s1, bufA, W[2], Bi[2], 64, 128, 256);
        conv_launch(bufA, bufB, W[3], Bi[3], 128, 128, 256);
        pool_launch(bufB, p2 + img * s2, 2 * 128, 128);
        conv_launch(p2 + img * s2, bufA, W[4], Bi[4], 128, 256, 128);
        conv_launch(bufA, bufB, W[5], Bi[5], 256, 256, 128);
        conv_launch(bufB, bufA, W[6], Bi[6], 256, 256, 128);
        pool_launch(bufA, p3 + img * s3, 2 * 256, 64);
    }

    // perceptual: always normalized by numel(pool_gt[0]) (faithful to reference bug)
    const double invNigt = 1.0 / 8388608.0;
    k_perc<<<1024, 256>>>(p1, p1 + s1, p1 + 2 * s1, (int)s1, invNigt);
    k_perc<<<1024, 256>>>(p2, p2 + s2, p2 + 2 * s2, (int)s2, invNigt);
    k_perc<<<1024, 256>>>(p3, p3 + s3, p3 + 2 * s3, (int)s3, invNigt);

    // style: scale = Kp / C^2 = 1/(C*H*W) / C^2   (H == W at every level)
    dim3 gb(16, 16);
    {
        double sc = 1.0 / (64.0 * 256.0 * 256.0) / (64.0 * 64.0);
        k_gram<<<dim3(4, 4, 2 * 64), gb>>>(p1 + s1, p1, p1 + 2 * s1, 256, sc);
    }
    {
        double sc = 1.0 / (128.0 * 128.0 * 128.0) / (128.0 * 128.0);
        k_gram<<<dim3(2, 2, 2 * 128), gb>>>(p2 + s2, p2, p2 + 2 * s2, 128, sc);
    }
    {
        double sc = 1.0 / (256.0 * 64.0 * 64.0) / (256.0 * 256.0);
        k_gram<<<dim3(1, 1, 2 * 256), gb>>>(p3 + s3, p3, p3 + 2 * s3, 64, sc);
    }

    k_final<<<1, 1>>>((float*)d_out);
}

// round 4
// speedup vs baseline: 2.3445x; 2.3445x over previous
#include <cuda_runtime.h>
#include <math.h>

// ---------------- scratch (device globals; allocation-free) ----------------
__device__ float d_bufA[33554432];
__device__ float d_bufB[33554432];
__device__ float d_compbuf[2 * 3 * 512 * 512];
__device__ float d_p1[3 * 2 * 64 * 256 * 256];
__device__ float d_p2[3 * 2 * 128 * 128 * 128];
__device__ float d_p3[3 * 2 * 256 * 64 * 64];
__device__ double d_loss;

// ---------------- f32x2 helpers ----------------
__device__ __forceinline__ unsigned long long pk2(float v) {
    unsigned long long r;
    asm("mov.b64 %0, {%1, %1};" : "=l"(r) : "r"(__float_as_uint(v)));
    return r;
}
__device__ __forceinline__ void fma2(unsigned long long& d, unsigned long long a,
                                     unsigned long long b) {
    asm("fma.rn.f32x2 %0, %1, %2, %0;" : "+l"(d) : "l"(a), "l"(b));
}
__device__ __forceinline__ void upk2(unsigned long long v, float& lo, float& hi) {
    unsigned ulo, uhi;
    asm("mov.b64 {%0, %1}, %2;" : "=r"(ulo), "=r"(uhi) : "l"(v));
    lo = __uint_as_float(ulo);
    hi = __uint_as_float(uhi);
}

// ---------------- reductions ----------------
__device__ __forceinline__ void block_reduce_add(float v, double scale) {
    __shared__ float red[256];
    int t = threadIdx.y * blockDim.x + threadIdx.x;
    red[t] = v;
    __syncthreads();
    for (int s = 128; s > 0; s >>= 1) {
        if (t < s) red[t] += red[t + s];
        __syncthreads();
    }
    if (t == 0) atomicAdd(&d_loss, scale * (double)red[0]);
}

__global__ void k_zero() { d_loss = 0.0; }
__global__ void k_final(float* out) { out[0] = (float)d_loss; }

// ---------------- composite image ----------------
__global__ void k_comp(const float* __restrict__ igt, const float* __restrict__ iout,
                       const float* __restrict__ mask) {
    const int HW2 = 512 * 512;
    const int n = 2 * 3 * HW2;
    int idx = blockIdx.x * blockDim.x + threadIdx.x;
    if (idx >= n) return;
    int b = idx / (3 * HW2);
    int p = idx % HW2;
    bool m = (mask[b * HW2 + p] != 0.0f);
    d_compbuf[idx] = m ? igt[idx] : iout[idx];
}

// ---------------- l_hole + l_valid ----------------
__global__ void k_holevalid(const float* __restrict__ igt, const float* __restrict__ iout,
                            const float* __restrict__ mask) {
    const int HW2 = 512 * 512;
    const int n = 2 * 3 * HW2;
    float s = 0.f;
    for (int idx = blockIdx.x * blockDim.x + threadIdx.x; idx < n;
         idx += gridDim.x * blockDim.x) {
        int b = idx / (3 * HW2);
        int p = idx % HW2;
        bool m = (mask[b * HW2 + p] != 0.0f);
        float d = fabsf(iout[idx] - igt[idx]);
        s += d * (m ? 1.0f : 2.0f);
    }
    block_reduce_add(s, 1.0 / (3.0 * 512.0 * 512.0 * 2.0));
}

// ---------------- perceptual L1 ----------------
__global__ void k_perc(const float* __restrict__ po, const float* __restrict__ pg,
                       const float* __restrict__ pc, int n, double scale) {
    float s = 0.f;
    for (int i = blockIdx.x * blockDim.x + threadIdx.x; i < n;
         i += gridDim.x * blockDim.x) {
        float g = pg[i];
        s += fabsf(po[i] - g) + fabsf(pc[i] - g);
    }
    block_reduce_add(s, scale);
}

// ---------------- 2x2 max pool ----------------
__global__ void k_pool(const float* __restrict__ in, float* __restrict__ out,
                       int BC, int Hout) {
    int n = BC * Hout * Hout;
    int idx = blockIdx.x * blockDim.x + threadIdx.x;
    if (idx >= n) return;
    int c = idx / (Hout * Hout);
    int r = idx % (Hout * Hout);
    int y = r / Hout, x = r % Hout;
    int Hin = Hout * 2;
    const float* p = in + ((size_t)c * Hin + 2 * y) * Hin + 2 * x;
    float v0 = fmaxf(p[0], p[1]);
    float v1 = fmaxf(p[Hin], p[Hin + 1]);
    out[idx] = fmaxf(v0, v1);
}

// ---------------- direct 3x3 conv, f32x2, cout-paired ----------------
// Block 256 = (32,8). Tile 32x32 pixels, 4 rows/thread, 8 couts/block (4 f32x2 pairs).
// Weights staged transposed [kc][k][cout] so {w_f, w_f+1} is one aligned LDS.64.
#define KCMAX 8
__global__ __launch_bounds__(256, 2) void k_conv2(
    const float* __restrict__ in, float* __restrict__ out,
    const float* __restrict__ wt, const float* __restrict__ bs,
    int Cin, int Cout, int HW) {
    __shared__ __align__(16) float sIn[KCMAX][34 * 34];
    __shared__ __align__(16) float sW[KCMAX][9][8];

    const int tx = threadIdx.x;   // 0..31
    const int ty = threadIdx.y;   // 0..7
    const int tid = ty * 32 + tx;
    const int cb = Cout >> 3;
    const int b = blockIdx.z / cb;
    const int c0 = (blockIdx.z % cb) * 8;
    const int x0 = blockIdx.x * 32, y0 = blockIdx.y * 32;
    const int KC = (Cin < KCMAX) ? Cin : KCMAX;

    unsigned long long acc[4][4];
    #pragma unroll
    for (int r = 0; r < 4; ++r)
        #pragma unroll
        for (int p = 0; p < 4; ++p) acc[r][p] = 0ull;

    const float* inB = in + (size_t)b * Cin * HW * HW;
    const size_t HW2 = (size_t)HW * HW;

    for (int cin0 = 0; cin0 < Cin; cin0 += KC) {
        __syncthreads();
        // stage KC input planes (34x34 halo tile each)
        const int NIN = KC * 1156;
        for (int i = tid; i < NIN; i += 256) {
            int kc = i / 1156;
            int r = i - kc * 1156;
            int py = r / 34, px = r - py * 34;
            int gy = y0 - 1 + py, gx = x0 - 1 + px;
            float v = 0.f;
            if ((unsigned)gy < (unsigned)HW && (unsigned)gx < (unsigned)HW)
                v = inB[(size_t)(cin0 + kc) * HW2 + (size_t)gy * HW + gx];
            sIn[kc][r] = v;
        }
        // stage weights transposed: sW[kc][k][f]
        const int NWT = KC * 72;
        for (int i = tid; i < NWT; i += 256) {
            int kc = i / 72;
            int r = i - kc * 72;
            int k = r >> 3, f = r & 7;
            sW[kc][k][f] = wt[(size_t)(c0 + f) * Cin * 9 + (size_t)(cin0 + kc) * 9 + k];
        }
        __syncthreads();

        for (int kc = 0; kc < KC; ++kc) {
            // 6 input rows x 3 cols, packed {v,v}
            unsigned long long ip[6][3];
            #pragma unroll
            for (int r = 0; r < 6; ++r)
                #pragma unroll
                for (int c = 0; c < 3; ++c)
                    ip[r][c] = pk2(sIn[kc][(4 * ty + r) * 34 + tx + c]);

            #pragma unroll
            for (int p = 0; p < 4; ++p) {
                #pragma unroll
                for (int k = 0; k < 9; ++k) {
                    unsigned long long w =
                        *(const unsigned long long*)&sW[kc][k][2 * p];
                    const int ky = k / 3, kx = k - 3 * (k / 3);
                    #pragma unroll
                    for (int r = 0; r < 4; ++r)
                        fma2(acc[r][p], ip[r + ky][kx], w);
                }
            }
        }
    }

    // epilogue: bias + relu + store (lo half = cout c0+2p, hi half = c0+2p+1)
    #pragma unroll
    for (int p = 0; p < 4; ++p) {
        float b0 = bs[c0 + 2 * p], b1 = bs[c0 + 2 * p + 1];
        #pragma unroll
        for (int r = 0; r < 4; ++r) {
            float lo, hi;
            upk2(acc[r][p], lo, hi);
            int y = y0 + 4 * ty + r, x = x0 + tx;
            size_t o = ((size_t)(b * Cout + c0 + 2 * p) * HW + y) * HW + x;
            out[o] = fmaxf(lo + b0, 0.f);
            out[o + HW2] = fmaxf(hi + b1, 0.f);
        }
    }
}
#undef KCMAX

// ---------------- fused style Gram kernel ----------------
__global__ __launch_bounds__(256) void k_gram(
    const float* __restrict__ g, const float* __restrict__ a0,
    const float* __restrict__ a1, int Wd, double scale) {
    const int jt = blockIdx.x, it = blockIdx.y;
    if (jt < it) return;

    __shared__ float sw[3][16][64];
    __shared__ float sv[3][16][64];
    const int tx = threadIdx.x, ty = threadIdx.y;
    const int tid = ty * 16 + tx;
    const size_t base = (size_t)blockIdx.z * Wd * Wd;
    const float* mats[3] = {g, a0, a1};

    float aG[16], aO[16], aC[16];
    #pragma unroll
    for (int i = 0; i < 16; ++i) { aG[i] = 0.f; aO[i] = 0.f; aC[i] = 0.f; }

    const int w0 = it * 64, v0 = jt * 64;
    for (int kb = 0; kb < Wd; kb += 16) {
        __syncthreads();
        for (int m = 0; m < 3; ++m) {
            const float* src = mats[m] + base + (size_t)kb * Wd;
            for (int i = tid; i < 1024; i += 256) {
                int kr = i >> 6, col = i & 63;
                sw[m][kr][col] = src[(size_t)kr * Wd + w0 + col];
                sv[m][kr][col] = src[(size_t)kr * Wd + v0 + col];
            }
        }
        __syncthreads();
        for (int k = 0; k < 16; ++k) {
            float gw[4], ow[4], cw[4], gv[4], ov[4], cv[4];
            #pragma unroll
            for (int r = 0; r < 4; ++r) {
                gw[r] = sw[0][k][ty + 16 * r];
                ow[r] = sw[1][k][ty + 16 * r];
                cw[r] = sw[2][k][ty + 16 * r];
                gv[r] = sv[0][k][tx + 16 * r];
                ov[r] = sv[1][k][tx + 16 * r];
                cv[r] = sv[2][k][tx + 16 * r];
            }
            #pragma unroll
            for (int r = 0; r < 4; ++r)
                #pragma unroll
                for (int s = 0; s < 4; ++s) {
                    aG[r * 4 + s] += gw[r] * gv[s];
                    aO[r * 4 + s] += ow[r] * ov[s];
                    aC[r * 4 + s] += cw[r] * cv[s];
                }
        }
    }

    float sum = 0.f;
    #pragma unroll
    for (int r = 0; r < 4; ++r)
        #pragma unroll
        for (int s = 0; s < 4; ++s) {
            int w = w0 + ty + 16 * r;
            int v = v0 + tx + 16 * s;
            float wgt = (jt > it) ? 2.f : (v > w ? 2.f : (v == w ? 1.f : 0.f));
            float gg = aG[r * 4 + s];
            sum += wgt * (fabsf(aO[r * 4 + s] - gg) + fabsf(aC[r * 4 + s] - gg));
        }
    block_reduce_add(sum, scale);
}

// ---------------- host orchestration ----------------
static void conv_launch(const float* in, float* out, const float* w, const float* b,
                        int Cin, int Cout, int HW) {
    dim3 grid(HW / 32, HW / 32, 2 * (Cout / 8));
    dim3 blk(32, 8);
    k_conv2<<<grid, blk>>>(in, out, w, b, Cin, Cout, HW);
}

static void pool_launch(const float* in, float* out, int BC, int Hout) {
    int n = BC * Hout * Hout;
    k_pool<<<(n + 255) / 256, 256>>>(in, out, BC, Hout);
}

extern "C" void kernel_launch(void* const* d_in, const int* in_sizes, int n_in,
                              void* d_out, int out_size) {
    const float* igt  = (const float*)d_in[0];
    const float* iout = (const float*)d_in[1];
    const float* mask = (const float*)d_in[2];
    const float* W[7];
    const float* Bi[7];
    for (int i = 0; i < 7; ++i) {
        W[i]  = (const float*)d_in[3 + 2 * i];
        Bi[i] = (const float*)d_in[4 + 2 * i];
    }

    float *bufA, *bufB, *comp, *p1, *p2, *p3;
    cudaGetSymbolAddress((void**)&bufA, d_bufA);
    cudaGetSymbolAddress((void**)&bufB, d_bufB);
    cudaGetSymbolAddress((void**)&comp, d_compbuf);
    cudaGetSymbolAddress((void**)&p1, d_p1);
    cudaGetSymbolAddress((void**)&p2, d_p2);
    cudaGetSymbolAddress((void**)&p3, d_p3);

    const size_t s1 = 2ull * 64 * 256 * 256;
    const size_t s2 = 2ull * 128 * 128 * 128;
    const size_t s3 = 2ull * 256 * 64 * 64;

    k_zero<<<1, 1>>>();

    const int nC = 2 * 3 * 512 * 512;
    k_comp<<<(nC + 255) / 256, 256>>>(igt, iout, mask);
    k_holevalid<<<1024, 256>>>(igt, iout, mask);

    for (int img = 0; img < 3; ++img) {
        const float* src = (img == 0) ? iout : (img == 1) ? igt : comp;
        conv_launch(src, bufA, W[0], Bi[0], 3, 64, 512);
        conv_launch(bufA, bufB, W[1], Bi[1], 64, 64, 512);
        pool_launch(bufB, p1 + img * s1, 2 * 64, 256);
        conv_launch(p1 + img * s1, bufA, W[2], Bi[2], 64, 128, 256);
        conv_launch(bufA, bufB, W[3], Bi[3], 128, 128, 256);
        pool_launch(bufB, p2 + img * s2, 2 * 128, 128);
        conv_launch(p2 + img * s2, bufA, W[4], Bi[4], 128, 256, 128);
        conv_launch(bufA, bufB, W[5], Bi[5], 256, 256, 128);
        conv_launch(bufB, bufA, W[6], Bi[6], 256, 256, 128);
        pool_launch(bufA, p3 + img * s3, 2 * 256, 64);
    }

    const double invNigt = 1.0 / 8388608.0;
    k_perc<<<1024, 256>>>(p1, p1 + s1, p1 + 2 * s1, (int)s1, invNigt);
    k_perc<<<1024, 256>>>(p2, p2 + s2, p2 + 2 * s2, (int)s2, invNigt);
    k_perc<<<1024, 256>>>(p3, p3 + s3, p3 + 2 * s3, (int)s3, invNigt);

    dim3 gb(16, 16);
    {
        double sc = 1.0 / (64.0 * 256.0 * 256.0) / (64.0 * 64.0);
        k_gram<<<dim3(4, 4, 2 * 64), gb>>>(p1 + s1, p1, p1 + 2 * s1, 256, sc);
    }
    {
        double sc = 1.0 / (128.0 * 128.0 * 128.0) / (128.0 * 128.0);
        k_gram<<<dim3(2, 2, 2 * 128), gb>>>(p2 + s2, p2, p2 + 2 * s2, 128, sc);
    }
    {
        double sc = 1.0 / (256.0 * 64.0 * 64.0) / (256.0 * 256.0);
        k_gram<<<dim3(1, 1, 2 * 256), gb>>>(p3 + s3, p3, p3 + 2 * s3, 64, sc);
    }

    k_final<<<1, 1>>>((float*)d_out);
}

// round 5
// speedup vs baseline: 2.9439x; 1.2557x over previous
#include <cuda_runtime.h>
#include <math.h>
#include <stdint.h>

// ---------------- scratch (device globals; allocation-free) ----------------
__device__ float d_bufA[33554432];
__device__ float d_bufB[33554432];
__device__ float d_compbuf[2 * 3 * 512 * 512];
__device__ float d_p1[3 * 2 * 64 * 256 * 256];
__device__ float d_p2[3 * 2 * 128 * 128 * 128];
__device__ float d_p3[3 * 2 * 256 * 64 * 64];
__device__ double d_loss;

// ---------------- f32x2 helpers ----------------
__device__ __forceinline__ unsigned long long pk2(float v) {
    unsigned long long r;
    asm("mov.b64 %0, {%1, %1};" : "=l"(r) : "r"(__float_as_uint(v)));
    return r;
}
__device__ __forceinline__ void fma2(unsigned long long& d, unsigned long long a,
                                     unsigned long long b) {
    asm("fma.rn.f32x2 %0, %1, %2, %0;" : "+l"(d) : "l"(a), "l"(b));
}
__device__ __forceinline__ void upk2(unsigned long long v, float& lo, float& hi) {
    unsigned ulo, uhi;
    asm("mov.b64 {%0, %1}, %2;" : "=r"(ulo), "=r"(uhi) : "l"(v));
    lo = __uint_as_float(ulo);
    hi = __uint_as_float(uhi);
}

// ---------------- cp.async helpers ----------------
__device__ __forceinline__ uint32_t s2u(const void* p) {
    return (uint32_t)__cvta_generic_to_shared(p);
}
// 4-byte async copy; zero-fills smem when !valid (CUTLASS zfill idiom: src-size=0)
__device__ __forceinline__ void cp_async4(uint32_t dst, const void* src, bool valid) {
    int sz = valid ? 4 : 0;
    asm volatile("cp.async.ca.shared.global [%0], [%1], 4, %2;\n"
                 :: "r"(dst), "l"(src), "r"(sz));
}
__device__ __forceinline__ void cp_commit() {
    asm volatile("cp.async.commit_group;\n");
}
template <int N>
__device__ __forceinline__ void cp_wait() {
    asm volatile("cp.async.wait_group %0;\n" :: "n"(N));
}

// ---------------- reductions ----------------
__device__ __forceinline__ void block_reduce_add(float v, double scale) {
    __shared__ float red[256];
    int t = threadIdx.y * blockDim.x + threadIdx.x;
    red[t] = v;
    __syncthreads();
    for (int s = 128; s > 0; s >>= 1) {
        if (t < s) red[t] += red[t + s];
        __syncthreads();
    }
    if (t == 0) atomicAdd(&d_loss, scale * (double)red[0]);
}

__global__ void k_zero() { d_loss = 0.0; }
__global__ void k_final(float* out) { out[0] = (float)d_loss; }

// ---------------- composite image ----------------
__global__ void k_comp(const float* __restrict__ igt, const float* __restrict__ iout,
                       const float* __restrict__ mask) {
    const int HW2 = 512 * 512;
    const int n = 2 * 3 * HW2;
    int idx = blockIdx.x * blockDim.x + threadIdx.x;
    if (idx >= n) return;
    int b = idx / (3 * HW2);
    int p = idx % HW2;
    bool m = (mask[b * HW2 + p] != 0.0f);
    d_compbuf[idx] = m ? igt[idx] : iout[idx];
}

// ---------------- l_hole + l_valid ----------------
__global__ void k_holevalid(const float* __restrict__ igt, const float* __restrict__ iout,
                            const float* __restrict__ mask) {
    const int HW2 = 512 * 512;
    const int n = 2 * 3 * HW2;
    float s = 0.f;
    for (int idx = blockIdx.x * blockDim.x + threadIdx.x; idx < n;
         idx += gridDim.x * blockDim.x) {
        int b = idx / (3 * HW2);
        int p = idx % HW2;
        bool m = (mask[b * HW2 + p] != 0.0f);
        float d = fabsf(iout[idx] - igt[idx]);
        s += d * (m ? 1.0f : 2.0f);
    }
    block_reduce_add(s, 1.0 / (3.0 * 512.0 * 512.0 * 2.0));
}

// ---------------- perceptual L1 ----------------
__global__ void k_perc(const float* __restrict__ po, const float* __restrict__ pg,
                       const float* __restrict__ pc, int n, double scale) {
    float s = 0.f;
    for (int i = blockIdx.x * blockDim.x + threadIdx.x; i < n;
         i += gridDim.x * blockDim.x) {
        float g = pg[i];
        s += fabsf(po[i] - g) + fabsf(pc[i] - g);
    }
    block_reduce_add(s, scale);
}

// ---------------- 2x2 max pool ----------------
__global__ void k_pool(const float* __restrict__ in, float* __restrict__ out,
                       int BC, int Hout) {
    int n = BC * Hout * Hout;
    int idx = blockIdx.x * blockDim.x + threadIdx.x;
    if (idx >= n) return;
    int c = idx / (Hout * Hout);
    int r = idx % (Hout * Hout);
    int y = r / Hout, x = r % Hout;
    int Hin = Hout * 2;
    const float* p = in + ((size_t)c * Hin + 2 * y) * Hin + 2 * x;
    float v0 = fmaxf(p[0], p[1]);
    float v1 = fmaxf(p[Hin], p[Hin + 1]);
    out[idx] = fmaxf(v0, v1);
}

// ---------------- direct 3x3 conv, f32x2, cp.async double-buffered ----------------
// Block 256 = (32,8). Tile 32x32 pixels, 4 rows/thread, 8 couts/block (4 f32x2 pairs).
// 2-stage ping-pong: KC=4 input planes per stage, prefetched via cp.async while the
// current stage computes. Weights staged transposed [kc][k][cout] -> LDS.64 pairs.
#define KC 4
__global__ __launch_bounds__(256, 2) void k_conv3(
    const float* __restrict__ in, float* __restrict__ out,
    const float* __restrict__ wt, const float* __restrict__ bs,
    int Cin, int Cout, int HW) {
    __shared__ __align__(16) float sIn[2][KC][34 * 34];
    __shared__ __align__(16) float sW[2][KC][9][8];

    const int tx = threadIdx.x;   // 0..31
    const int ty = threadIdx.y;   // 0..7
    const int tid = ty * 32 + tx;
    const int cb = Cout >> 3;
    const int b = blockIdx.z / cb;
    const int c0 = (blockIdx.z % cb) * 8;
    const int x0 = blockIdx.x * 32, y0 = blockIdx.y * 32;

    unsigned long long acc[4][4];
    #pragma unroll
    for (int r = 0; r < 4; ++r)
        #pragma unroll
        for (int p = 0; p < 4; ++p) acc[r][p] = 0ull;

    const float* inB = in + (size_t)b * Cin * HW * HW;
    const size_t HW2 = (size_t)HW * HW;
    const int nCh = (Cin + KC - 1) / KC;

    // ---- async fill of one stage ----
    auto fill = [&](int s, int cin0) {
        #pragma unroll
        for (int kc = 0; kc < KC; ++kc) {
            const bool pv = (cin0 + kc) < Cin;
            const float* ip = inB + (size_t)(cin0 + kc) * HW2;
            #pragma unroll
            for (int j0 = 0; j0 < 1156; j0 += 256) {
                int j = j0 + tid;
                if (j < 1156) {
                    int py = j / 34, px = j - py * 34;
                    int gy = y0 - 1 + py, gx = x0 - 1 + px;
                    bool v = pv && (unsigned)gy < (unsigned)HW &&
                             (unsigned)gx < (unsigned)HW;
                    cp_async4(s2u(&sIn[s][kc][j]),
                              ip + (size_t)gy * HW + gx, v);
                }
            }
        }
        // weights: KC*72 = 288 scalars
        for (int i = tid; i < KC * 72; i += 256) {
            int kc = i / 72;
            int r = i - kc * 72;
            int k = r >> 3, f = r & 7;
            bool v = (cin0 + kc) < Cin;
            cp_async4(s2u(&sW[s][kc][k][f]),
                      wt + (size_t)(c0 + f) * Cin * 9 + (size_t)(cin0 + kc) * 9 + k,
                      v);
        }
        cp_commit();
    };

    fill(0, 0);

    for (int ch = 0; ch < nCh; ++ch) {
        const int s = ch & 1;
        if (ch + 1 < nCh) {
            fill(s ^ 1, (ch + 1) * KC);
            cp_wait<1>();
        } else {
            cp_wait<0>();
        }
        __syncthreads();

        #pragma unroll
        for (int kc = 0; kc < KC; ++kc) {
            unsigned long long ip[6][3];
            #pragma unroll
            for (int r = 0; r < 6; ++r)
                #pragma unroll
                for (int c = 0; c < 3; ++c)
                    ip[r][c] = pk2(sIn[s][kc][(4 * ty + r) * 34 + tx + c]);

            #pragma unroll
            for (int p = 0; p < 4; ++p) {
                #pragma unroll
                for (int k = 0; k < 9; ++k) {
                    unsigned long long w =
                        *(const unsigned long long*)&sW[s][kc][k][2 * p];
                    const int ky = k / 3, kx = k - 3 * (k / 3);
                    #pragma unroll
                    for (int r = 0; r < 4; ++r)
                        fma2(acc[r][p], ip[r + ky][kx], w);
                }
            }
        }
        __syncthreads();   // stage s will be refilled next iteration
    }

    // epilogue: bias + relu + store (lo half = cout c0+2p, hi half = c0+2p+1)
    #pragma unroll
    for (int p = 0; p < 4; ++p) {
        float b0 = bs[c0 + 2 * p], b1 = bs[c0 + 2 * p + 1];
        #pragma unroll
        for (int r = 0; r < 4; ++r) {
            float lo, hi;
            upk2(acc[r][p], lo, hi);
            int y = y0 + 4 * ty + r, x = x0 + tx;
            size_t o = ((size_t)(b * Cout + c0 + 2 * p) * HW + y) * HW + x;
            out[o] = fmaxf(lo + b0, 0.f);
            out[o + HW2] = fmaxf(hi + b1, 0.f);
        }
    }
}
#undef KC

// ---------------- fused style Gram kernel ----------------
__global__ __launch_bounds__(256) void k_gram(
    const float* __restrict__ g, const float* __restrict__ a0,
    const float* __restrict__ a1, int Wd, double scale) {
    const int jt = blockIdx.x, it = blockIdx.y;
    if (jt < it) return;

    __shared__ float sw[3][16][64];
    __shared__ float sv[3][16][64];
    const int tx = threadIdx.x, ty = threadIdx.y;
    const int tid = ty * 16 + tx;
    const size_t base = (size_t)blockIdx.z * Wd * Wd;
    const float* mats[3] = {g, a0, a1};

    float aG[16], aO[16], aC[16];
    #pragma unroll
    for (int i = 0; i < 16; ++i) { aG[i] = 0.f; aO[i] = 0.f; aC[i] = 0.f; }

    const int w0 = it * 64, v0 = jt * 64;
    for (int kb = 0; kb < Wd; kb += 16) {
        __syncthreads();
        for (int m = 0; m < 3; ++m) {
            const float* src = mats[m] + base + (size_t)kb * Wd;
            for (int i = tid; i < 1024; i += 256) {
                int kr = i >> 6, col = i & 63;
                sw[m][kr][col] = src[(size_t)kr * Wd + w0 + col];
                sv[m][kr][col] = src[(size_t)kr * Wd + v0 + col];
            }
        }
        __syncthreads();
        for (int k = 0; k < 16; ++k) {
            float gw[4], ow[4], cw[4], gv[4], ov[4], cv[4];
            #pragma unroll
            for (int r = 0; r < 4; ++r) {
                gw[r] = sw[0][k][ty + 16 * r];
                ow[r] = sw[1][k][ty + 16 * r];
                cw[r] = sw[2][k][ty + 16 * r];
                gv[r] = sv[0][k][tx + 16 * r];
                ov[r] = sv[1][k][tx + 16 * r];
                cv[r] = sv[2][k][tx + 16 * r];
            }
            #pragma unroll
            for (int r = 0; r < 4; ++r)
                #pragma unroll
                for (int s = 0; s < 4; ++s) {
                    aG[r * 4 + s] += gw[r] * gv[s];
                    aO[r * 4 + s] += ow[r] * ov[s];
                    aC[r * 4 + s] += cw[r] * cv[s];
                }
        }
    }

    float sum = 0.f;
    #pragma unroll
    for (int r = 0; r < 4; ++r)
        #pragma unroll
        for (int s = 0; s < 4; ++s) {
            int w = w0 + ty + 16 * r;
            int v = v0 + tx + 16 * s;
            float wgt = (jt > it) ? 2.f : (v > w ? 2.f : (v == w ? 1.f : 0.f));
            float gg = aG[r * 4 + s];
            sum += wgt * (fabsf(aO[r * 4 + s] - gg) + fabsf(aC[r * 4 + s] - gg));
        }
    block_reduce_add(sum, scale);
}

// ---------------- host orchestration ----------------
static void conv_launch(const float* in, float* out, const float* w, const float* b,
                        int Cin, int Cout, int HW) {
    dim3 grid(HW / 32, HW / 32, 2 * (Cout / 8));
    dim3 blk(32, 8);
    k_conv3<<<grid, blk>>>(in, out, w, b, Cin, Cout, HW);
}

static void pool_launch(const float* in, float* out, int BC, int Hout) {
    int n = BC * Hout * Hout;
    k_pool<<<(n + 255) / 256, 256>>>(in, out, BC, Hout);
}

extern "C" void kernel_launch(void* const* d_in, const int* in_sizes, int n_in,
                              void* d_out, int out_size) {
    const float* igt  = (const float*)d_in[0];
    const float* iout = (const float*)d_in[1];
    const float* mask = (const float*)d_in[2];
    const float* W[7];
    const float* Bi[7];
    for (int i = 0; i < 7; ++i) {
        W[i]  = (const float*)d_in[3 + 2 * i];
        Bi[i] = (const float*)d_in[4 + 2 * i];
    }

    float *bufA, *bufB, *comp, *p1, *p2, *p3;
    cudaGetSymbolAddress((void**)&bufA, d_bufA);
    cudaGetSymbolAddress((void**)&bufB, d_bufB);
    cudaGetSymbolAddress((void**)&comp, d_compbuf);
    cudaGetSymbolAddress((void**)&p1, d_p1);
    cudaGetSymbolAddress((void**)&p2, d_p2);
    cudaGetSymbolAddress((void**)&p3, d_p3);

    const size_t s1 = 2ull * 64 * 256 * 256;
    const size_t s2 = 2ull * 128 * 128 * 128;
    const size_t s3 = 2ull * 256 * 64 * 64;

    k_zero<<<1, 1>>>();

    const int nC = 2 * 3 * 512 * 512;
    k_comp<<<(nC + 255) / 256, 256>>>(igt, iout, mask);
    k_holevalid<<<1024, 256>>>(igt, iout, mask);

    for (int img = 0; img < 3; ++img) {
        const float* src = (img == 0) ? iout : (img == 1) ? igt : comp;
        conv_launch(src, bufA, W[0], Bi[0], 3, 64, 512);
        conv_launch(bufA, bufB, W[1], Bi[1], 64, 64, 512);
        pool_launch(bufB, p1 + img * s1, 2 * 64, 256);
        conv_launch(p1 + img * s1, bufA, W[2], Bi[2], 64, 128, 256);
        conv_launch(bufA, bufB, W[3], Bi[3], 128, 128, 256);
        pool_launch(bufB, p2 + img * s2, 2 * 128, 128);
        conv_launch(p2 + img * s2, bufA, W[4], Bi[4], 128, 256, 128);
        conv_launch(bufA, bufB, W[5], Bi[5], 256, 256, 128);
        conv_launch(bufB, bufA, W[6], Bi[6], 256, 256, 128);
        pool_launch(bufA, p3 + img * s3, 2 * 256, 64);
    }

    const double invNigt = 1.0 / 8388608.0;
    k_perc<<<1024, 256>>>(p1, p1 + s1, p1 + 2 * s1, (int)s1, invNigt);
    k_perc<<<1024, 256>>>(p2, p2 + s2, p2 + 2 * s2, (int)s2, invNigt);
    k_perc<<<1024, 256>>>(p3, p3 + s3, p3 + 2 * s3, (int)s3, invNigt);

    dim3 gb(16, 16);
    {
        double sc = 1.0 / (64.0 * 256.0 * 256.0) / (64.0 * 64.0);
        k_gram<<<dim3(4, 4, 2 * 64), gb>>>(p1 + s1, p1, p1 + 2 * s1, 256, sc);
    }
    {
        double sc = 1.0 / (128.0 * 128.0 * 128.0) / (128.0 * 128.0);
        k_gram<<<dim3(2, 2, 2 * 128), gb>>>(p2 + s2, p2, p2 + 2 * s2, 128, sc);
    }
    {
        double sc = 1.0 / (256.0 * 64.0 * 64.0) / (256.0 * 256.0);
        k_gram<<<dim3(1, 1, 2 * 256), gb>>>(p3 + s3, p3, p3 + 2 * s3, 64, sc);
    }

    k_final<<<1, 1>>>((float*)d_out);
}

// round 7
// speedup vs baseline: 13.2440x; 4.4988x over previous
#include <cuda_runtime.h>
#include <cuda_bf16.h>
#include <math.h>
#include <stdint.h>

// ================= scratch (device globals; allocation-free) =================
__device__ __nv_bfloat16 d_tA[33554432];           // NHWC activations ping
__device__ __nv_bfloat16 d_tB[33554432];           // NHWC activations pong
__device__ __nv_bfloat16 d_wtb[1732608];           // [shift][cout][cin] bf16 weights, layers 1-6
__device__ float d_compbuf[2 * 3 * 512 * 512];
__device__ float d_p1[3 * 2 * 64 * 256 * 256];
__device__ float d_p2[3 * 2 * 128 * 128 * 128];
__device__ float d_p3[3 * 2 * 256 * 64 * 64];
__device__ double d_loss;

// ================= helpers =================
__device__ __forceinline__ uint32_t s2u(const void* p) {
    return (uint32_t)__cvta_generic_to_shared(p);
}
__device__ __forceinline__ void cp_async16(uint32_t dst, const void* src, bool valid) {
    int sz = valid ? 16 : 0;
    asm volatile("cp.async.cg.shared.global [%0], [%1], 16, %2;\n"
                 :: "r"(dst), "l"(src), "r"(sz));
}
__device__ __forceinline__ void cp_commit() {
    asm volatile("cp.async.commit_group;\n");
}
template <int N>
__device__ __forceinline__ void cp_wait() {
    asm volatile("cp.async.wait_group %0;\n" :: "n"(N));
}

// f32x2 (layer0)
__device__ __forceinline__ unsigned long long pk2(float v) {
    unsigned long long r;
    asm("mov.b64 %0, {%1, %1};" : "=l"(r) : "r"(__float_as_uint(v)));
    return r;
}
__device__ __forceinline__ void fma2(unsigned long long& d, unsigned long long a,
                                     unsigned long long b) {
    asm("fma.rn.f32x2 %0, %1, %2, %0;" : "+l"(d) : "l"(a), "l"(b));
}
__device__ __forceinline__ void upk2(unsigned long long v, float& lo, float& hi) {
    unsigned ulo, uhi;
    asm("mov.b64 {%0, %1}, %2;" : "=r"(ulo), "=r"(uhi) : "l"(v));
    lo = __uint_as_float(ulo);
    hi = __uint_as_float(uhi);
}

// warp MMA primitives (sm_80+; legal on base sm_103 target)
__device__ __forceinline__ void ldsm4(uint32_t& r0, uint32_t& r1, uint32_t& r2,
                                      uint32_t& r3, uint32_t addr) {
    asm volatile("ldmatrix.sync.aligned.m8n8.x4.shared.b16 {%0,%1,%2,%3}, [%4];"
                 : "=r"(r0), "=r"(r1), "=r"(r2), "=r"(r3) : "r"(addr));
}
__device__ __forceinline__ void mma16816(float* c, const uint32_t* a,
                                         const uint32_t* b) {
    asm volatile(
        "mma.sync.aligned.m16n8k16.row.col.f32.bf16.bf16.f32 "
        "{%0,%1,%2,%3}, {%4,%5,%6,%7}, {%8,%9}, {%0,%1,%2,%3};"
        : "+f"(c[0]), "+f"(c[1]), "+f"(c[2]), "+f"(c[3])
        : "r"(a[0]), "r"(a[1]), "r"(a[2]), "r"(a[3]), "r"(b[0]), "r"(b[1]));
}

// ================= reductions =================
__device__ __forceinline__ void block_reduce_add(float v, double scale) {
    __shared__ float red[256];
    int t = threadIdx.y * blockDim.x + threadIdx.x;
    red[t] = v;
    __syncthreads();
    for (int s = 128; s > 0; s >>= 1) {
        if (t < s) red[t] += red[t + s];
        __syncthreads();
    }
    if (t == 0) atomicAdd(&d_loss, scale * (double)red[0]);
}

__global__ void k_zero() { d_loss = 0.0; }
__global__ void k_final(float* out) { out[0] = (float)d_loss; }

// ================= composite / hole+valid / perc =================
__global__ void k_comp(const float* __restrict__ igt, const float* __restrict__ iout,
                       const float* __restrict__ mask) {
    const int HW2 = 512 * 512;
    const int n = 2 * 3 * HW2;
    int idx = blockIdx.x * blockDim.x + threadIdx.x;
    if (idx >= n) return;
    int b = idx / (3 * HW2);
    int p = idx % HW2;
    bool m = (mask[b * HW2 + p] != 0.0f);
    d_compbuf[idx] = m ? igt[idx] : iout[idx];
}

__global__ void k_holevalid(const float* __restrict__ igt, const float* __restrict__ iout,
                            const float* __restrict__ mask) {
    const int HW2 = 512 * 512;
    const int n = 2 * 3 * HW2;
    float s = 0.f;
    for (int idx = blockIdx.x * blockDim.x + threadIdx.x; idx < n;
         idx += gridDim.x * blockDim.x) {
        int b = idx / (3 * HW2);
        int p = idx % HW2;
        bool m = (mask[b * HW2 + p] != 0.0f);
        float d = fabsf(iout[idx] - igt[idx]);
        s += d * (m ? 1.0f : 2.0f);
    }
    block_reduce_add(s, 1.0 / (3.0 * 512.0 * 512.0 * 2.0));
}

__global__ void k_perc(const float* __restrict__ po, const float* __restrict__ pg,
                       const float* __restrict__ pc, int n, double scale) {
    float s = 0.f;
    for (int i = blockIdx.x * blockDim.x + threadIdx.x; i < n;
         i += gridDim.x * blockDim.x) {
        float g = pg[i];
        s += fabsf(po[i] - g) + fabsf(pc[i] - g);
    }
    block_reduce_add(s, scale);
}

// ================= weight transform: OIHW fp32 -> [shift][cout][cin] bf16 =======
__global__ void k_wt(const float* __restrict__ w, __nv_bfloat16* __restrict__ dst,
                     int Cout, int Cin) {
    int n = 9 * Cout * Cin;
    int idx = blockIdx.x * blockDim.x + threadIdx.x;
    if (idx >= n) return;
    int sh = idx / (Cout * Cin);
    int r = idx - sh * Cout * Cin;
    int co = r / Cin, ci = r - co * Cin;
    dst[idx] = __float2bfloat16(w[((size_t)co * Cin + ci) * 9 + sh]);
}

// ================= layer0: 3->64 FFMA2 conv, NCHW fp32 -> NHWC bf16 ===========
__global__ __launch_bounds__(256, 2) void k_conv0(
    const float* __restrict__ in, __nv_bfloat16* __restrict__ out,
    const float* __restrict__ wt, const float* __restrict__ bs) {
    const int HW = 512;
    __shared__ __align__(16) float sIn[3][34 * 34];
    __shared__ __align__(16) float sW[3][9][8];

    const int tx = threadIdx.x, ty = threadIdx.y;
    const int tid = ty * 32 + tx;
    const int b = blockIdx.z >> 3;
    const int c0 = (blockIdx.z & 7) * 8;
    const int x0 = blockIdx.x * 32, y0 = blockIdx.y * 32;

    const float* inB = in + (size_t)b * 3 * HW * HW;
    for (int i = tid; i < 3 * 1156; i += 256) {
        int kc = i / 1156;
        int r = i - kc * 1156;
        int py = r / 34, px = r - py * 34;
        int gy = y0 - 1 + py, gx = x0 - 1 + px;
        float v = 0.f;
        if ((unsigned)gy < (unsigned)HW && (unsigned)gx < (unsigned)HW)
            v = inB[(size_t)kc * HW * HW + (size_t)gy * HW + gx];
        sIn[kc][r] = v;
    }
    for (int i = tid; i < 3 * 72; i += 256) {
        int kc = i / 72;
        int r = i - kc * 72;
        int k = r >> 3, f = r & 7;
        sW[kc][k][f] = wt[(size_t)(c0 + f) * 27 + kc * 9 + k];
    }
    __syncthreads();

    unsigned long long acc[4][4];
    #pragma unroll
    for (int r = 0; r < 4; ++r)
        #pragma unroll
        for (int p = 0; p < 4; ++p) acc[r][p] = 0ull;

    #pragma unroll
    for (int kc = 0; kc < 3; ++kc) {
        unsigned long long ip[6][3];
        #pragma unroll
        for (int r = 0; r < 6; ++r)
            #pragma unroll
            for (int c = 0; c < 3; ++c)
                ip[r][c] = pk2(sIn[kc][(4 * ty + r) * 34 + tx + c]);
        #pragma unroll
        for (int p = 0; p < 4; ++p) {
            #pragma unroll
            for (int k = 0; k < 9; ++k) {
                unsigned long long w = *(const unsigned long long*)&sW[kc][k][2 * p];
                const int ky = k / 3, kx = k - 3 * (k / 3);
                #pragma unroll
                for (int r = 0; r < 4; ++r)
                    fma2(acc[r][p], ip[r + ky][kx], w);
            }
        }
    }

    #pragma unroll
    for (int r = 0; r < 4; ++r) {
        uint32_t pk[4];
        #pragma unroll
        for (int p = 0; p < 4; ++p) {
            float lo, hi;
            upk2(acc[r][p], lo, hi);
            lo = fmaxf(lo + bs[c0 + 2 * p], 0.f);
            hi = fmaxf(hi + bs[c0 + 2 * p + 1], 0.f);
            uint32_t l16 = (uint32_t)__bfloat16_as_ushort(__float2bfloat16(lo));
            uint32_t h16 = (uint32_t)__bfloat16_as_ushort(__float2bfloat16(hi));
            pk[p] = l16 | (h16 << 16);
        }
        int y = y0 + 4 * ty + r, x = x0 + tx;
        size_t p = (size_t)b * HW * HW + (size_t)y * HW + x;
        *(uint4*)(out + p * 64 + c0) = make_uint4(pk[0], pk[1], pk[2], pk[3]);
    }
}

// ================= warp-MMA implicit-GEMM 3x3 conv (NHWC bf16) ================
// D[cout(MT), pixel(NT)] = sum over 9 shifts x 64-cin chunks; A=weights K-major,
// B=shifted NHWC pixel rows K-major. mma.sync m16n8k16 bf16 -> fp32.
template <int MT, int NT>
__global__ __launch_bounds__(256) void k_convmma(
    const __nv_bfloat16* __restrict__ in, __nv_bfloat16* __restrict__ out,
    const __nv_bfloat16* __restrict__ wt, const float* __restrict__ bs,
    int Cin, int Cout, int H, int W) {
    constexpr int WM = (MT == 128) ? 2 : 1;   // warps along M
    constexpr int STR = 72;                   // smem row stride (bf16), 144B
    constexpr int OSTR = MT + 8;              // out staging stride (bf16)
    constexpr int AB_BYTES = (MT + NT) * STR * 2;
    constexpr int OB_BYTES = NT * OSTR * 2;
    constexpr int SBYTES = AB_BYTES > OB_BYTES ? AB_BYTES : OB_BYTES;
    __shared__ __align__(16) char smem[SBYTES];
    __nv_bfloat16* sA = (__nv_bfloat16*)smem;
    __nv_bfloat16* sB = sA + MT * STR;
    const uint32_t sAu = s2u(sA), sBu = s2u(sB);

    const int tid = threadIdx.x;
    const int lane = tid & 31, wid = tid >> 5;
    const int warpM = wid % WM, warpN = wid / WM;

    const int tileP = blockIdx.x * NT;
    const int b = tileP / (H * W);
    const int rem = tileP - b * H * W;
    const int y = rem / W, x0 = rem - (rem / W) * W;
    const int coutBase = blockIdx.y * MT;

    float acc[4][4][4];
    #pragma unroll
    for (int mi = 0; mi < 4; ++mi)
        #pragma unroll
        for (int nj = 0; nj < 4; ++nj)
            #pragma unroll
            for (int e = 0; e < 4; ++e) acc[mi][nj][e] = 0.f;

    const int nCh = Cin >> 6;

    for (int sh = 0; sh < 9; ++sh) {
        const int ky = sh / 3 - 1, kx = sh - 3 * (sh / 3) - 1;
        const __nv_bfloat16* wsh = wt + ((size_t)sh * Cout + coutBase) * Cin;
        const int ys = y + ky;
        const bool rowv = (unsigned)ys < (unsigned)H;
        const __nv_bfloat16* inrow = in + ((size_t)(b * H + ys) * W) * Cin;

        for (int ch = 0; ch < nCh; ++ch) {
            const int c0 = ch * 64;
            __syncthreads();   // previous chunk's mma readers done
            // A: MT rows x 64 k (8 x 16B per row)
            for (int o = tid; o < MT * 8; o += 256) {
                int row = o >> 3, seg = o & 7;
                cp_async16(sAu + (row * STR + seg * 8) * 2,
                           wsh + (size_t)row * Cin + c0 + seg * 8, true);
            }
            // B: NT pixel rows x 64 k, zfill halo
            for (int o = tid; o < NT * 8; o += 256) {
                int j = o >> 3, seg = o & 7;
                int xs = x0 + kx + j;
                bool v = rowv && (unsigned)xs < (unsigned)W;
                cp_async16(sBu + (j * STR + seg * 8) * 2,
                           inrow + (size_t)xs * Cin + c0 + seg * 8, v);
            }
            cp_commit();
            cp_wait<0>();
            __syncthreads();

            #pragma unroll
            for (int ks = 0; ks < 4; ++ks) {
                const int kk = ks * 16;
                uint32_t af[4][4];
                #pragma unroll
                for (int mi = 0; mi < 4; ++mi) {
                    int row = warpM * 64 + mi * 16 + (lane & 7) + ((lane >> 3) & 1) * 8;
                    int col = kk + (lane >> 4) * 8;
                    ldsm4(af[mi][0], af[mi][1], af[mi][2], af[mi][3],
                          sAu + (row * STR + col) * 2);
                }
                uint32_t bf[4][2];
                #pragma unroll
                for (int pj = 0; pj < 2; ++pj) {
                    int row = warpN * 32 + pj * 16 + (lane & 7) + (lane >> 4) * 8;
                    int col = kk + ((lane >> 3) & 1) * 8;
                    uint32_t r0, r1, r2, r3;
                    ldsm4(r0, r1, r2, r3, sBu + (row * STR + col) * 2);
                    bf[2 * pj][0] = r0; bf[2 * pj][1] = r1;
                    bf[2 * pj + 1][0] = r2; bf[2 * pj + 1][1] = r3;
                }
                #pragma unroll
                for (int mi = 0; mi < 4; ++mi)
                    #pragma unroll
                    for (int nj = 0; nj < 4; ++nj)
                        mma16816(acc[mi][nj], af[mi], bf[nj]);
            }
        }
    }

    // ---- epilogue: bias + relu -> smem [pixel][cout] -> coalesced NHWC stores
    __syncthreads();
    __nv_bfloat16* ob = (__nv_bfloat16*)smem;
    #pragma unroll
    for (int mi = 0; mi < 4; ++mi) {
        int m = warpM * 64 + mi * 16 + (lane >> 2);
        float bv0 = bs[coutBase + m];
        float bv1 = bs[coutBase + m + 8];
        #pragma unroll
        for (int nj = 0; nj < 4; ++nj) {
            int n = warpN * 32 + nj * 8 + (lane & 3) * 2;
            float* c = acc[mi][nj];
            ob[n * OSTR + m]           = __float2bfloat16(fmaxf(c[0] + bv0, 0.f));
            ob[(n + 1) * OSTR + m]     = __float2bfloat16(fmaxf(c[1] + bv0, 0.f));
            ob[n * OSTR + m + 8]       = __float2bfloat16(fmaxf(c[2] + bv1, 0.f));
            ob[(n + 1) * OSTR + m + 8] = __float2bfloat16(fmaxf(c[3] + bv1, 0.f));
        }
    }
    __syncthreads();
    constexpr int HALF = MT / 2;
    for (int o = tid; o < NT * HALF; o += 256) {
        int row = o / HALF, cp = o - row * HALF;
        uint32_t v = *(const uint32_t*)&ob[row * OSTR + cp * 2];
        *(uint32_t*)&out[(size_t)(tileP + row) * Cout + coutBase + cp * 2] = v;
    }
}

// ================= pool: NHWC bf16 -> NCHW fp32 (+ optional NHWC bf16) ========
__global__ __launch_bounds__(256) void k_poolT(
    const __nv_bfloat16* __restrict__ in, float* __restrict__ outN,
    __nv_bfloat16* __restrict__ outT, int C, int Ho, int Wo) {
    __shared__ float s[32][65];
    const int tid = threadIdx.x;
    const int p0 = blockIdx.x * 32;
    const int c0 = blockIdx.y * 64;
    const int b = blockIdx.z;
    const int W = Wo * 2;
    const __nv_bfloat16* inb = in + (size_t)b * (Ho * 2) * W * C;

    #pragma unroll
    for (int e = 0; e < 8; ++e) {
        int elem = tid + 256 * e;
        int c = elem & 63, pix = elem >> 6;
        int p = p0 + pix;
        int yy = p / Wo, xx = p - yy * Wo;
        const __nv_bfloat16* q = inb + ((size_t)(2 * yy) * W + 2 * xx) * C + c0 + c;
        float v0 = __bfloat162float(q[0]);
        float v1 = __bfloat162float(q[C]);
        float v2 = __bfloat162float(q[(size_t)W * C]);
        float v3 = __bfloat162float(q[(size_t)W * C + C]);
        float m = fmaxf(fmaxf(v0, v1), fmaxf(v2, v3));
        s[pix][c] = m;
        if (outT)
            outT[((size_t)b * Ho * Wo + p) * C + c0 + c] = __float2bfloat16(m);
    }
    __syncthreads();
    #pragma unroll
    for (int e = 0; e < 8; ++e) {
        int elem = tid + 256 * e;
        int pix = elem & 31, c = elem >> 5;
        outN[((size_t)(b * C + c0 + c)) * Ho * Wo + p0 + pix] = s[pix][c];
    }
}

// ================= fused style Gram kernel (NCHW fp32 pools) =================
__global__ __launch_bounds__(256) void k_gram(
    const float* __restrict__ g, const float* __restrict__ a0,
    const float* __restrict__ a1, int Wd, double scale) {
    const int jt = blockIdx.x, it = blockIdx.y;
    if (jt < it) return;

    __shared__ float sw[3][16][64];
    __shared__ float sv[3][16][64];
    const int tx = threadIdx.x, ty = threadIdx.y;
    const int tid = ty * 16 + tx;
    const size_t base = (size_t)blockIdx.z * Wd * Wd;
    const float* mats[3] = {g, a0, a1};

    float aG[16], aO[16], aC[16];
    #pragma unroll
    for (int i = 0; i < 16; ++i) { aG[i] = 0.f; aO[i] = 0.f; aC[i] = 0.f; }

    const int w0 = it * 64, v0 = jt * 64;
    for (int kb = 0; kb < Wd; kb += 16) {
        __syncthreads();
        for (int m = 0; m < 3; ++m) {
            const float* src = mats[m] + base + (size_t)kb * Wd;
            for (int i = tid; i < 1024; i += 256) {
                int kr = i >> 6, col = i & 63;
                sw[m][kr][col] = src[(size_t)kr * Wd + w0 + col];
                sv[m][kr][col] = src[(size_t)kr * Wd + v0 + col];
            }
        }
        __syncthreads();
        for (int k = 0; k < 16; ++k) {
            float gw[4], ow[4], cw[4], gv[4], ov[4], cv[4];
            #pragma unroll
            for (int r = 0; r < 4; ++r) {
                gw[r] = sw[0][k][ty + 16 * r];
                ow[r] = sw[1][k][ty + 16 * r];
                cw[r] = sw[2][k][ty + 16 * r];
                gv[r] = sv[0][k][tx + 16 * r];
                ov[r] = sv[1][k][tx + 16 * r];
                cv[r] = sv[2][k][tx + 16 * r];
            }
            #pragma unroll
            for (int r = 0; r < 4; ++r)
                #pragma unroll
                for (int s = 0; s < 4; ++s) {
                    aG[r * 4 + s] += gw[r] * gv[s];
                    aO[r * 4 + s] += ow[r] * ov[s];
                    aC[r * 4 + s] += cw[r] * cv[s];
                }
        }
    }

    float sum = 0.f;
    #pragma unroll
    for (int r = 0; r < 4; ++r)
        #pragma unroll
        for (int s = 0; s < 4; ++s) {
            int w = w0 + ty + 16 * r;
            int v = v0 + tx + 16 * s;
            float wgt = (jt > it) ? 2.f : (v > w ? 2.f : (v == w ? 1.f : 0.f));
            float gg = aG[r * 4 + s];
            sum += wgt * (fabsf(aO[r * 4 + s] - gg) + fabsf(aC[r * 4 + s] - gg));
        }
    block_reduce_add(sum, scale);
}

// ================= host orchestration =================
extern "C" void kernel_launch(void* const* d_in, const int* in_sizes, int n_in,
                              void* d_out, int out_size) {
    const float* igt  = (const float*)d_in[0];
    const float* iout = (const float*)d_in[1];
    const float* mask = (const float*)d_in[2];
    const float* W[7];
    const float* Bi[7];
    for (int i = 0; i < 7; ++i) {
        W[i]  = (const float*)d_in[3 + 2 * i];
        Bi[i] = (const float*)d_in[4 + 2 * i];
    }

    __nv_bfloat16 *tA, *tB, *wtb;
    float *comp, *p1, *p2, *p3;
    cudaGetSymbolAddress((void**)&tA, d_tA);
    cudaGetSymbolAddress((void**)&tB, d_tB);
    cudaGetSymbolAddress((void**)&wtb, d_wtb);
    cudaGetSymbolAddress((void**)&comp, d_compbuf);
    cudaGetSymbolAddress((void**)&p1, d_p1);
    cudaGetSymbolAddress((void**)&p2, d_p2);
    cudaGetSymbolAddress((void**)&p3, d_p3);

    const size_t s1 = 2ull * 64 * 256 * 256;
    const size_t s2 = 2ull * 128 * 128 * 128;
    const size_t s3 = 2ull * 256 * 64 * 64;

    // wt offsets (elements) for layers 1..6 ; {Cout, Cin}
    const size_t wo[6] = {0, 36864, 110592, 258048, 552960, 1142784};
    const int wc[6][2] = {{64, 64}, {128, 64}, {128, 128},
                          {256, 128}, {256, 256}, {256, 256}};

    k_zero<<<1, 1>>>();

    const int nC = 2 * 3 * 512 * 512;
    k_comp<<<(nC + 255) / 256, 256>>>(igt, iout, mask);
    k_holevalid<<<1024, 256>>>(igt, iout, mask);

    for (int l = 0; l < 6; ++l) {
        int n = 9 * wc[l][0] * wc[l][1];
        k_wt<<<(n + 255) / 256, 256>>>(W[l + 1], wtb + wo[l], wc[l][0], wc[l][1]);
    }

    for (int img = 0; img < 3; ++img) {
        const float* src = (img == 0) ? iout : (img == 1) ? igt : comp;
        // layer0: 3->64 @512, NCHW fp32 -> NHWC bf16
        k_conv0<<<dim3(16, 16, 16), dim3(32, 8)>>>(src, tA, W[0], Bi[0]);
        // l1: 64->64 @512 (MT=64, NT=256)
        k_convmma<64, 256><<<dim3(2048, 1), 256>>>(tA, tB, wtb + wo[0], Bi[1],
                                                   64, 64, 512, 512);
        k_poolT<<<dim3(2048, 1, 2), 256>>>(tB, p1 + img * s1, tA, 64, 256, 256);
        // l2: 64->128 @256
        k_convmma<128, 128><<<dim3(1024, 1), 256>>>(tA, tB, wtb + wo[1], Bi[2],
                                                    64, 128, 256, 256);
        // l3: 128->128 @256
        k_convmma<128, 128><<<dim3(1024, 1), 256>>>(tB, tA, wtb + wo[2], Bi[3],
                                                    128, 128, 256, 256);
        k_poolT<<<dim3(512, 2, 2), 256>>>(tA, p2 + img * s2, tB, 128, 128, 128);
        // l4: 128->256 @128
        k_convmma<128, 128><<<dim3(256, 2), 256>>>(tB, tA, wtb + wo[3], Bi[4],
                                                   128, 256, 128, 128);
        // l5: 256->256 @128
        k_convmma<128, 128><<<dim3(256, 2), 256>>>(tA, tB, wtb + wo[4], Bi[5],
                                                   256, 256, 128, 128);
        // l6: 256->256 @128
        k_convmma<128, 128><<<dim3(256, 2), 256>>>(tB, tA, wtb + wo[5], Bi[6],
                                                   256, 256, 128, 128);
        k_poolT<<<dim3(128, 4, 2), 256>>>(tA, p3 + img * s3, (__nv_bfloat16*)nullptr,
                                          256, 64, 64);
    }

    const double invNigt = 1.0 / 8388608.0;
    k_perc<<<1024, 256>>>(p1, p1 + s1, p1 + 2 * s1, (int)s1, invNigt);
    k_perc<<<1024, 256>>>(p2, p2 + s2, p2 + 2 * s2, (int)s2, invNigt);
    k_perc<<<1024, 256>>>(p3, p3 + s3, p3 + 2 * s3, (int)s3, invNigt);

    dim3 gb(16, 16);
    {
        double sc = 1.0 / (64.0 * 256.0 * 256.0) / (64.0 * 64.0);
        k_gram<<<dim3(4, 4, 2 * 64), gb>>>(p1 + s1, p1, p1 + 2 * s1, 256, sc);
    }
    {
        double sc = 1.0 / (128.0 * 128.0 * 128.0) / (128.0 * 128.0);
        k_gram<<<dim3(2, 2, 2 * 128), gb>>>(p2 + s2, p2, p2 + 2 * s2, 128, sc);
    }
    {
        double sc = 1.0 / (256.0 * 64.0 * 64.0) / (256.0 * 256.0);
        k_gram<<<dim3(1, 1, 2 * 256), gb>>>(p3 + s3, p3, p3 + 2 * s3, 64, sc);
    }

    k_final<<<1, 1>>>((float*)d_out);
}

// round 8
// speedup vs baseline: 13.2514x; 1.0006x over previous
#include <cuda_runtime.h>
#include <cuda_bf16.h>
#include <math.h>
#include <stdint.h>

// ================= scratch (device globals; allocation-free) =================
__device__ __nv_bfloat16 d_tA[33554432];           // NHWC activations ping
__device__ __nv_bfloat16 d_tB[33554432];           // NHWC activations pong
__device__ __nv_bfloat16 d_wtb[1732608];           // [shift][cout][cin] bf16 weights
__device__ float d_compbuf[2 * 3 * 512 * 512];
__device__ float d_p1[3 * 2 * 64 * 256 * 256];
__device__ float d_p2[3 * 2 * 128 * 128 * 128];
__device__ float d_p3[3 * 2 * 256 * 64 * 64];
__device__ double d_loss;

// ================= helpers =================
__device__ __forceinline__ uint32_t s2u(const void* p) {
    return (uint32_t)__cvta_generic_to_shared(p);
}
__device__ __forceinline__ void cp_async16(uint32_t dst, const void* src, bool valid) {
    int sz = valid ? 16 : 0;
    asm volatile("cp.async.cg.shared.global [%0], [%1], 16, %2;\n"
                 :: "r"(dst), "l"(src), "r"(sz));
}
__device__ __forceinline__ void cp_commit() {
    asm volatile("cp.async.commit_group;\n");
}
template <int N>
__device__ __forceinline__ void cp_wait() {
    asm volatile("cp.async.wait_group %0;\n" :: "n"(N));
}

// f32x2 (layer0)
__device__ __forceinline__ unsigned long long pk2(float v) {
    unsigned long long r;
    asm("mov.b64 %0, {%1, %1};" : "=l"(r) : "r"(__float_as_uint(v)));
    return r;
}
__device__ __forceinline__ void fma2(unsigned long long& d, unsigned long long a,
                                     unsigned long long b) {
    asm("fma.rn.f32x2 %0, %1, %2, %0;" : "+l"(d) : "l"(a), "l"(b));
}
__device__ __forceinline__ void upk2(unsigned long long v, float& lo, float& hi) {
    unsigned ulo, uhi;
    asm("mov.b64 {%0, %1}, %2;" : "=r"(ulo), "=r"(uhi) : "l"(v));
    lo = __uint_as_float(ulo);
    hi = __uint_as_float(uhi);
}

// warp MMA primitives (sm_80+, legal on base sm_103 target)
__device__ __forceinline__ void ldsm4(uint32_t& r0, uint32_t& r1, uint32_t& r2,
                                      uint32_t& r3, uint32_t addr) {
    asm volatile("ldmatrix.sync.aligned.m8n8.x4.shared.b16 {%0,%1,%2,%3}, [%4];"
                 : "=r"(r0), "=r"(r1), "=r"(r2), "=r"(r3) : "r"(addr));
}
__device__ __forceinline__ void mma16816(float* c, const uint32_t* a,
                                         const uint32_t* b) {
    asm volatile(
        "mma.sync.aligned.m16n8k16.row.col.f32.bf16.bf16.f32 "
        "{%0,%1,%2,%3}, {%4,%5,%6,%7}, {%8,%9}, {%0,%1,%2,%3};"
        : "+f"(c[0]), "+f"(c[1]), "+f"(c[2]), "+f"(c[3])
        : "r"(a[0]), "r"(a[1]), "r"(a[2]), "r"(a[3]), "r"(b[0]), "r"(b[1]));
}

// ================= reductions =================
__device__ __forceinline__ void block_reduce_add(float v, double scale) {
    __shared__ float red[256];
    int t = threadIdx.y * blockDim.x + threadIdx.x;
    red[t] = v;
    __syncthreads();
    for (int s = 128; s > 0; s >>= 1) {
        if (t < s) red[t] += red[t + s];
        __syncthreads();
    }
    if (t == 0) atomicAdd(&d_loss, scale * (double)red[0]);
}

__global__ void k_zero() { d_loss = 0.0; }
__global__ void k_final(float* out) { out[0] = (float)d_loss; }

// ================= composite / hole+valid / perc =================
__global__ void k_comp(const float* __restrict__ igt, const float* __restrict__ iout,
                       const float* __restrict__ mask) {
    const int HW2 = 512 * 512;
    const int n = 2 * 3 * HW2;
    int idx = blockIdx.x * blockDim.x + threadIdx.x;
    if (idx >= n) return;
    int b = idx / (3 * HW2);
    int p = idx % HW2;
    bool m = (mask[b * HW2 + p] != 0.0f);
    d_compbuf[idx] = m ? igt[idx] : iout[idx];
}

__global__ void k_holevalid(const float* __restrict__ igt, const float* __restrict__ iout,
                            const float* __restrict__ mask) {
    const int HW2 = 512 * 512;
    const int n = 2 * 3 * HW2;
    float s = 0.f;
    for (int idx = blockIdx.x * blockDim.x + threadIdx.x; idx < n;
         idx += gridDim.x * blockDim.x) {
        int b = idx / (3 * HW2);
        int p = idx % HW2;
        bool m = (mask[b * HW2 + p] != 0.0f);
        float d = fabsf(iout[idx] - igt[idx]);
        s += d * (m ? 1.0f : 2.0f);
    }
    block_reduce_add(s, 1.0 / (3.0 * 512.0 * 512.0 * 2.0));
}

__global__ void k_perc(const float* __restrict__ po, const float* __restrict__ pg,
                       const float* __restrict__ pc, int n, double scale) {
    float s = 0.f;
    for (int i = blockIdx.x * blockDim.x + threadIdx.x; i < n;
         i += gridDim.x * blockDim.x) {
        float g = pg[i];
        s += fabsf(po[i] - g) + fabsf(pc[i] - g);
    }
    block_reduce_add(s, scale);
}

// ================= weight transform: OIHW fp32 -> [shift][cout][cin] bf16 =======
__global__ void k_wt(const float* __restrict__ w, __nv_bfloat16* __restrict__ dst,
                     int Cout, int Cin) {
    int n = 9 * Cout * Cin;
    int idx = blockIdx.x * blockDim.x + threadIdx.x;
    if (idx >= n) return;
    int sh = idx / (Cout * Cin);
    int r = idx - sh * (Cout * Cin);
    int co = r / Cin, ci = r - co * Cin;
    dst[idx] = __float2bfloat16(w[((size_t)co * Cin + ci) * 9 + sh]);
}

// ================= layer0: 3->64 FFMA2 conv, NCHW fp32 -> NHWC bf16 ===========
__global__ __launch_bounds__(256, 2) void k_conv0(
    const float* __restrict__ in, __nv_bfloat16* __restrict__ out,
    const float* __restrict__ wt, const float* __restrict__ bs) {
    const int HW = 512;
    __shared__ __align__(16) float sIn[3][34 * 34];
    __shared__ __align__(16) float sW[3][9][8];

    const int tx = threadIdx.x, ty = threadIdx.y;
    const int tid = ty * 32 + tx;
    const int b = blockIdx.z >> 3;
    const int c0 = (blockIdx.z & 7) * 8;
    const int x0 = blockIdx.x * 32, y0 = blockIdx.y * 32;

    const float* inB = in + (size_t)b * 3 * HW * HW;
    for (int i = tid; i < 3 * 1156; i += 256) {
        int kc = i / 1156;
        int r = i - kc * 1156;
        int py = r / 34, px = r - py * 34;
        int gy = y0 - 1 + py, gx = x0 - 1 + px;
        float v = 0.f;
        if ((unsigned)gy < (unsigned)HW && (unsigned)gx < (unsigned)HW)
            v = inB[(size_t)kc * HW * HW + (size_t)gy * HW + gx];
        sIn[kc][r] = v;
    }
    for (int i = tid; i < 3 * 72; i += 256) {
        int kc = i / 72;
        int r = i - kc * 72;
        int k = r >> 3, f = r & 7;
        sW[kc][k][f] = wt[(size_t)(c0 + f) * 27 + kc * 9 + k];
    }
    __syncthreads();

    unsigned long long acc[4][4];
    #pragma unroll
    for (int r = 0; r < 4; ++r)
        #pragma unroll
        for (int p = 0; p < 4; ++p) acc[r][p] = 0ull;

    #pragma unroll
    for (int kc = 0; kc < 3; ++kc) {
        unsigned long long ip[6][3];
        #pragma unroll
        for (int r = 0; r < 6; ++r)
            #pragma unroll
            for (int c = 0; c < 3; ++c)
                ip[r][c] = pk2(sIn[kc][(4 * ty + r) * 34 + tx + c]);
        #pragma unroll
        for (int p = 0; p < 4; ++p) {
            #pragma unroll
            for (int k = 0; k < 9; ++k) {
                unsigned long long w = *(const unsigned long long*)&sW[kc][k][2 * p];
                const int ky = k / 3, kx = k - 3 * (k / 3);
                #pragma unroll
                for (int r = 0; r < 4; ++r)
                    fma2(acc[r][p], ip[r + ky][kx], w);
            }
        }
    }

    #pragma unroll
    for (int r = 0; r < 4; ++r) {
        uint32_t pk[4];
        #pragma unroll
        for (int p = 0; p < 4; ++p) {
            float lo, hi;
            upk2(acc[r][p], lo, hi);
            lo = fmaxf(lo + bs[c0 + 2 * p], 0.f);
            hi = fmaxf(hi + bs[c0 + 2 * p + 1], 0.f);
            uint32_t l16 = (uint32_t)__bfloat16_as_ushort(__float2bfloat16(lo));
            uint32_t h16 = (uint32_t)__bfloat16_as_ushort(__float2bfloat16(hi));
            pk[p] = l16 | (h16 << 16);
        }
        int y = y0 + 4 * ty + r, x = x0 + tx;
        size_t p = (size_t)b * HW * HW + (size_t)y * HW + x;
        *(uint4*)(out + p * 64 + c0) = make_uint4(pk[0], pk[1], pk[2], pk[3]);
    }
}

// ================= warp-MMA implicit-GEMM 3x3 conv, double-buffered ==========
template <int MT, int NT>
__global__ __launch_bounds__(256) void k_convmma(
    const __nv_bfloat16* __restrict__ in, __nv_bfloat16* __restrict__ out,
    const __nv_bfloat16* __restrict__ wt, const float* __restrict__ bs,
    int Cin, int Cout, int H, int W) {
    constexpr int WM = (MT == 128) ? 2 : 1;
    constexpr int STR = 72;                   // smem row stride (bf16)
    constexpr int OSTR = MT + 8;
    constexpr int STAGE = (MT + NT) * STR;    // bf16 elems per stage
    extern __shared__ __align__(16) char dsm[];
    __nv_bfloat16* st = (__nv_bfloat16*)dsm;

    const int tid = threadIdx.x;
    const int lane = tid & 31, wid = tid >> 5;
    const int warpM = wid % WM, warpN = wid / WM;

    const int tileP = blockIdx.x * NT;
    const int b = tileP / (H * W);
    const int rem = tileP - b * H * W;
    const int y = rem / W, x0 = rem - (rem / W) * W;
    const int coutBase = blockIdx.y * MT;

    float acc[4][4][4];
    #pragma unroll
    for (int mi = 0; mi < 4; ++mi)
        #pragma unroll
        for (int nj = 0; nj < 4; ++nj)
            #pragma unroll
            for (int e = 0; e < 4; ++e) acc[mi][nj][e] = 0.f;

    const int nCh = Cin >> 6;
    const int NI = 9 * nCh;

    uint32_t sAu[2], sBu[2];
    sAu[0] = s2u(st);
    sBu[0] = sAu[0] + MT * STR * 2;
    sAu[1] = s2u(st + STAGE);
    sBu[1] = sAu[1] + MT * STR * 2;

    auto fill = [&](int it, int buf) {
        const int sh = it / nCh;
        const int ch = it - sh * nCh;
        const int ky = sh / 3 - 1, kx = sh - 3 * (sh / 3) - 1;
        const int c0 = ch * 64;
        const __nv_bfloat16* wsh = wt + ((size_t)sh * Cout + coutBase) * Cin;
        const int ys = y + ky;
        const bool rowv = (unsigned)ys < (unsigned)H;
        const __nv_bfloat16* inrow = in + ((size_t)(b * H + ys) * W) * Cin;
        for (int o = tid; o < MT * 8; o += 256) {
            int row = o >> 3, seg = o & 7;
            cp_async16(sAu[buf] + (row * STR + seg * 8) * 2,
                       wsh + (size_t)row * Cin + c0 + seg * 8, true);
        }
        for (int o = tid; o < NT * 8; o += 256) {
            int j = o >> 3, seg = o & 7;
            int xs = x0 + kx + j;
            bool v = rowv && (unsigned)xs < (unsigned)W;
            cp_async16(sBu[buf] + (j * STR + seg * 8) * 2,
                       inrow + (size_t)xs * Cin + c0 + seg * 8, v);
        }
        cp_commit();
    };

    fill(0, 0);

    for (int it = 0; it < NI; ++it) {
        const int s = it & 1;
        if (it + 1 < NI) {
            fill(it + 1, s ^ 1);
            cp_wait<1>();
        } else {
            cp_wait<0>();
        }
        __syncthreads();

        #pragma unroll
        for (int ks = 0; ks < 4; ++ks) {
            const int kk = ks * 16;
            uint32_t af[4][4];
            #pragma unroll
            for (int mi = 0; mi < 4; ++mi) {
                int row = warpM * 64 + mi * 16 + (lane & 7) + ((lane >> 3) & 1) * 8;
                int col = kk + (lane >> 4) * 8;
                ldsm4(af[mi][0], af[mi][1], af[mi][2], af[mi][3],
                      sAu[s] + (row * STR + col) * 2);
            }
            uint32_t bf[4][2];
            #pragma unroll
            for (int pj = 0; pj < 2; ++pj) {
                int row = warpN * 32 + pj * 16 + (lane & 7) + (lane >> 4) * 8;
                int col = kk + ((lane >> 3) & 1) * 8;
                uint32_t r0, r1, r2, r3;
                ldsm4(r0, r1, r2, r3, sBu[s] + (row * STR + col) * 2);
                bf[2 * pj][0] = r0; bf[2 * pj][1] = r1;
                bf[2 * pj + 1][0] = r2; bf[2 * pj + 1][1] = r3;
            }
            #pragma unroll
            for (int mi = 0; mi < 4; ++mi)
                #pragma unroll
                for (int nj = 0; nj < 4; ++nj)
                    mma16816(acc[mi][nj], af[mi], bf[nj]);
        }
        __syncthreads();   // protect buf s^1 (next fill target) and buf s reuse
    }

    // ---- epilogue: bias + relu -> smem [pixel][cout] -> coalesced NHWC stores
    __nv_bfloat16* ob = (__nv_bfloat16*)dsm;
    #pragma unroll
    for (int mi = 0; mi < 4; ++mi) {
        int m = warpM * 64 + mi * 16 + (lane >> 2);
        float bv0 = bs[coutBase + m];
        float bv1 = bs[coutBase + m + 8];
        #pragma unroll
        for (int nj = 0; nj < 4; ++nj) {
            int n = warpN * 32 + nj * 8 + (lane & 3) * 2;
            float* c = acc[mi][nj];
            ob[n * OSTR + m]           = __float2bfloat16(fmaxf(c[0] + bv0, 0.f));
            ob[(n + 1) * OSTR + m]     = __float2bfloat16(fmaxf(c[1] + bv0, 0.f));
            ob[n * OSTR + m + 8]       = __float2bfloat16(fmaxf(c[2] + bv1, 0.f));
            ob[(n + 1) * OSTR + m + 8] = __float2bfloat16(fmaxf(c[3] + bv1, 0.f));
        }
    }
    __syncthreads();
    constexpr int HALF = MT / 2;
    for (int o = tid; o < NT * HALF; o += 256) {
        int row = o / HALF, cp = o - row * HALF;
        uint32_t v = *(const uint32_t*)&ob[row * OSTR + cp * 2];
        *(uint32_t*)&out[(size_t)(tileP + row) * Cout + coutBase + cp * 2] = v;
    }
}

// ================= pool: NHWC bf16 -> NCHW fp32 (+ optional NHWC bf16) ========
__global__ __launch_bounds__(256) void k_poolT(
    const __nv_bfloat16* __restrict__ in, float* __restrict__ outN,
    __nv_bfloat16* __restrict__ outT, int C, int Ho, int Wo) {
    __shared__ float s[32][65];
    const int tid = threadIdx.x;
    const int p0 = blockIdx.x * 32;
    const int c0 = blockIdx.y * 64;
    const int b = blockIdx.z;
    const int W = Wo * 2;
    const __nv_bfloat16* inb = in + (size_t)b * (Ho * 2) * W * C;

    #pragma unroll
    for (int e = 0; e < 8; ++e) {
        int elem = tid + 256 * e;
        int c = elem & 63, pix = elem >> 6;
        int p = p0 + pix;
        int yy = p / Wo, xx = p - yy * Wo;
        const __nv_bfloat16* q = inb + ((size_t)(2 * yy) * W + 2 * xx) * C + c0 + c;
        float v0 = __bfloat162float(q[0]);
        float v1 = __bfloat162float(q[C]);
        float v2 = __bfloat162float(q[(size_t)W * C]);
        float v3 = __bfloat162float(q[(size_t)W * C + C]);
        float m = fmaxf(fmaxf(v0, v1), fmaxf(v2, v3));
        s[pix][c] = m;
        if (outT)
            outT[((size_t)b * Ho * Wo + p) * C + c0 + c] = __float2bfloat16(m);
    }
    __syncthreads();
    #pragma unroll
    for (int e = 0; e < 8; ++e) {
        int elem = tid + 256 * e;
        int pix = elem & 31, c = elem >> 5;
        outN[((size_t)(b * C + c0 + c)) * Ho * Wo + p0 + pix] = s[pix][c];
    }
}

// ================= tensor-core style Gram kernel =============================
// Per (b,c): G[w,v] = sum_h Phi[h,w] Phi[h,v] for gt/out/comp simultaneously.
// Tile pair (it<=jt) of 64x64; smem holds transposed [w][h] bf16 slices.
__global__ __launch_bounds__(256) void k_gram_mma(
    const float* __restrict__ g, const float* __restrict__ a0,
    const float* __restrict__ a1, int Wd, int nT, double scale) {
    __shared__ __align__(16) __nv_bfloat16 sT[3][2][64][24];
    const int tid = threadIdx.x;
    const int lane = tid & 31, wid = tid >> 5;
    const int warpM = wid & 3, warpN = wid >> 2;

    // decode tile pair (it <= jt)
    int p = blockIdx.x, it = 0;
    while (p >= nT - it) { p -= nT - it; ++it; }
    const int jt = it + p;
    const int w0 = it * 64, v0 = jt * 64;

    const size_t base = (size_t)blockIdx.y * Wd * Wd;
    const float* mats[3] = {g, a0, a1};

    float acc[3][4][4];
    #pragma unroll
    for (int m = 0; m < 3; ++m)
        #pragma unroll
        for (int nj = 0; nj < 4; ++nj)
            #pragma unroll
            for (int e = 0; e < 4; ++e) acc[m][nj][e] = 0.f;

    const int nChunks = Wd >> 4;
    for (int kb = 0; kb < nChunks; ++kb) {
        __syncthreads();
        // stage: transpose fp32 Phi[h][w] -> bf16 sT[mat][slice][w][h]
        for (int o = tid; o < 6144; o += 256) {
            int mat = o / 2048;
            int r = o - mat * 2048;
            int sl = r >> 10;
            int e = r & 1023;
            int h = e >> 6, w = e & 63;
            int col0 = sl ? v0 : w0;
            float f = mats[mat][base + (size_t)(kb * 16 + h) * Wd + col0 + w];
            sT[mat][sl][w][h] = __float2bfloat16(f);
        }
        __syncthreads();

        #pragma unroll
        for (int mat = 0; mat < 3; ++mat) {
            uint32_t af[4];
            {
                int row = warpM * 16 + (lane & 7) + ((lane >> 3) & 1) * 8;
                int col = (lane >> 4) * 8;
                ldsm4(af[0], af[1], af[2], af[3],
                      s2u(&sT[mat][0][row][col]));
            }
            uint32_t bf[4][2];
            #pragma unroll
            for (int pj = 0; pj < 2; ++pj) {
                int row = warpN * 32 + pj * 16 + (lane & 7) + (lane >> 4) * 8;
                int col = ((lane >> 3) & 1) * 8;
                uint32_t r0, r1, r2, r3;
                ldsm4(r0, r1, r2, r3, s2u(&sT[mat][1][row][col]));
                bf[2 * pj][0] = r0; bf[2 * pj][1] = r1;
                bf[2 * pj + 1][0] = r2; bf[2 * pj + 1][1] = r3;
            }
            #pragma unroll
            for (int nj = 0; nj < 4; ++nj)
                mma16816(acc[mat][nj], af, bf[nj]);
        }
    }

    // epilogue: weighted |G_out - G_gt| + |G_comp - G_gt|
    float sum = 0.f;
    #pragma unroll
    for (int nj = 0; nj < 4; ++nj) {
        #pragma unroll
        for (int e = 0; e < 4; ++e) {
            int w = w0 + warpM * 16 + (lane >> 2) + (e >= 2 ? 8 : 0);
            int v = v0 + warpN * 32 + nj * 8 + (lane & 3) * 2 + (e & 1);
            float wgt = (jt > it) ? 2.f : (v > w ? 2.f : (v == w ? 1.f : 0.f));
            float gg = acc[0][nj][e];
            sum += wgt * (fabsf(acc[1][nj][e] - gg) + fabsf(acc[2][nj][e] - gg));
        }
    }
    block_reduce_add(sum, scale);
}

// ================= host orchestration =================
extern "C" void kernel_launch(void* const* d_in, const int* in_sizes, int n_in,
                              void* d_out, int out_size) {
    const float* igt  = (const float*)d_in[0];
    const float* iout = (const float*)d_in[1];
    const float* mask = (const float*)d_in[2];
    const float* W[7];
    const float* Bi[7];
    for (int i = 0; i < 7; ++i) {
        W[i]  = (const float*)d_in[3 + 2 * i];
        Bi[i] = (const float*)d_in[4 + 2 * i];
    }

    __nv_bfloat16 *tA, *tB, *wtb;
    float *comp, *p1, *p2, *p3;
    cudaGetSymbolAddress((void**)&tA, d_tA);
    cudaGetSymbolAddress((void**)&tB, d_tB);
    cudaGetSymbolAddress((void**)&wtb, d_wtb);
    cudaGetSymbolAddress((void**)&comp, d_compbuf);
    cudaGetSymbolAddress((void**)&p1, d_p1);
    cudaGetSymbolAddress((void**)&p2, d_p2);
    cudaGetSymbolAddress((void**)&p3, d_p3);

    const size_t s1 = 2ull * 64 * 256 * 256;
    const size_t s2 = 2ull * 128 * 128 * 128;
    const size_t s3 = 2ull * 256 * 64 * 64;

    const size_t wo[6] = {0, 36864, 110592, 258048, 552960, 1142784};
    const int wc[6][2] = {{64, 64}, {128, 64}, {128, 128},
                          {256, 128}, {256, 256}, {256, 256}};

    // dynamic smem opt-in (idempotent)
    const int SM1 = 2 * (64 + 256) * 72 * 2;    // 92160
    const int SM2 = 2 * (128 + 128) * 72 * 2;   // 73728
    cudaFuncSetAttribute(k_convmma<64, 256>,
                         cudaFuncAttributeMaxDynamicSharedMemorySize, SM1);
    cudaFuncSetAttribute(k_convmma<128, 128>,
                         cudaFuncAttributeMaxDynamicSharedMemorySize, SM2);

    k_zero<<<1, 1>>>();

    const int nC = 2 * 3 * 512 * 512;
    k_comp<<<(nC + 255) / 256, 256>>>(igt, iout, mask);
    k_holevalid<<<1024, 256>>>(igt, iout, mask);

    for (int l = 0; l < 6; ++l) {
        int n = 9 * wc[l][0] * wc[l][1];
        k_wt<<<(n + 255) / 256, 256>>>(W[l + 1], wtb + wo[l], wc[l][0], wc[l][1]);
    }

    for (int img = 0; img < 3; ++img) {
        const float* src = (img == 0) ? iout : (img == 1) ? igt : comp;
        k_conv0<<<dim3(16, 16, 16), dim3(32, 8)>>>(src, tA, W[0], Bi[0]);
        k_convmma<64, 256><<<dim3(2048, 1), 256, SM1>>>(tA, tB, wtb + wo[0], Bi[1],
                                                        64, 64, 512, 512);
        k_poolT<<<dim3(2048, 1, 2), 256>>>(tB, p1 + img * s1, tA, 64, 256, 256);
        k_convmma<128, 128><<<dim3(1024, 1), 256, SM2>>>(tA, tB, wtb + wo[1], Bi[2],
                                                         64, 128, 256, 256);
        k_convmma<128, 128><<<dim3(1024, 1), 256, SM2>>>(tB, tA, wtb + wo[2], Bi[3],
                                                         128, 128, 256, 256);
        k_poolT<<<dim3(512, 2, 2), 256>>>(tA, p2 + img * s2, tB, 128, 128, 128);
        k_convmma<128, 128><<<dim3(256, 2), 256, SM2>>>(tB, tA, wtb + wo[3], Bi[4],
                                                        128, 256, 128, 128);
        k_convmma<128, 128><<<dim3(256, 2), 256, SM2>>>(tA, tB, wtb + wo[4], Bi[5],
                                                        256, 256, 128, 128);
        k_convmma<128, 128><<<dim3(256, 2), 256, SM2>>>(tB, tA, wtb + wo[5], Bi[6],
                                                        256, 256, 128, 128);
        k_poolT<<<dim3(128, 4, 2), 256>>>(tA, p3 + img * s3, (__nv_bfloat16*)nullptr,
                                          256, 64, 64);
    }

    const double invNigt = 1.0 / 8388608.0;
    k_perc<<<1024, 256>>>(p1, p1 + s1, p1 + 2 * s1, (int)s1, invNigt);
    k_perc<<<1024, 256>>>(p2, p2 + s2, p2 + 2 * s2, (int)s2, invNigt);
    k_perc<<<1024, 256>>>(p3, p3 + s3, p3 + 2 * s3, (int)s3, invNigt);

    {
        double sc = 1.0 / (64.0 * 256.0 * 256.0) / (64.0 * 64.0);
        k_gram_mma<<<dim3(10, 2 * 64), 256>>>(p1 + s1, p1, p1 + 2 * s1, 256, 4, sc);
    }
    {
        double sc = 1.0 / (128.0 * 128.0 * 128.0) / (128.0 * 128.0);
        k_gram_mma<<<dim3(3, 2 * 128), 256>>>(p2 + s2, p2, p2 + 2 * s2, 128, 2, sc);
    }
    {
        double sc = 1.0 / (256.0 * 64.0 * 64.0) / (256.0 * 256.0);
        k_gram_mma<<<dim3(1, 2 * 256), 256>>>(p3 + s3, p3, p3 + 2 * s3, 64, 1, sc);
    }

    k_final<<<1, 1>>>((float*)d_out);
}

// round 9
// speedup vs baseline: 14.2212x; 1.0732x over previous
#include <cuda_runtime.h>
#include <cuda_bf16.h>
#include <math.h>
#include <stdint.h>

// ================= scratch (device globals; allocation-free) =================
__device__ __nv_bfloat16 d_tA[33554432];           // NHWC activations ping
__device__ __nv_bfloat16 d_tB[33554432];           // NHWC activations pong
__device__ __nv_bfloat16 d_wtb[1732608];           // [shift][cout][cin] bf16 weights
__device__ float d_compbuf[2 * 3 * 512 * 512];
__device__ float d_p1[3 * 2 * 64 * 256 * 256];
__device__ float d_p2[3 * 2 * 128 * 128 * 128];
__device__ float d_p3[3 * 2 * 256 * 64 * 64];
__device__ double d_loss;

// ================= helpers =================
__device__ __forceinline__ uint32_t s2u(const void* p) {
    return (uint32_t)__cvta_generic_to_shared(p);
}
__device__ __forceinline__ void cp_async16(uint32_t dst, const void* src, bool valid) {
    int sz = valid ? 16 : 0;
    asm volatile("cp.async.cg.shared.global [%0], [%1], 16, %2;\n"
                 :: "r"(dst), "l"(src), "r"(sz));
}
__device__ __forceinline__ void cp_commit() {
    asm volatile("cp.async.commit_group;\n");
}
template <int N>
__device__ __forceinline__ void cp_wait() {
    asm volatile("cp.async.wait_group %0;\n" :: "n"(N));
}

// f32x2 (layer0)
__device__ __forceinline__ unsigned long long pk2(float v) {
    unsigned long long r;
    asm("mov.b64 %0, {%1, %1};" : "=l"(r) : "r"(__float_as_uint(v)));
    return r;
}
__device__ __forceinline__ void fma2(unsigned long long& d, unsigned long long a,
                                     unsigned long long b) {
    asm("fma.rn.f32x2 %0, %1, %2, %0;" : "+l"(d) : "l"(a), "l"(b));
}
__device__ __forceinline__ void upk2(unsigned long long v, float& lo, float& hi) {
    unsigned ulo, uhi;
    asm("mov.b64 {%0, %1}, %2;" : "=r"(ulo), "=r"(uhi) : "l"(v));
    lo = __uint_as_float(ulo);
    hi = __uint_as_float(uhi);
}

// warp MMA primitives (sm_80+, legal on base sm_103 target)
__device__ __forceinline__ void ldsm4(uint32_t& r0, uint32_t& r1, uint32_t& r2,
                                      uint32_t& r3, uint32_t addr) {
    asm volatile("ldmatrix.sync.aligned.m8n8.x4.shared.b16 {%0,%1,%2,%3}, [%4];"
                 : "=r"(r0), "=r"(r1), "=r"(r2), "=r"(r3) : "r"(addr));
}
__device__ __forceinline__ void mma16816(float* c, const uint32_t* a,
                                         const uint32_t* b) {
    asm volatile(
        "mma.sync.aligned.m16n8k16.row.col.f32.bf16.bf16.f32 "
        "{%0,%1,%2,%3}, {%4,%5,%6,%7}, {%8,%9}, {%0,%1,%2,%3};"
        : "+f"(c[0]), "+f"(c[1]), "+f"(c[2]), "+f"(c[3])
        : "r"(a[0]), "r"(a[1]), "r"(a[2]), "r"(a[3]), "r"(b[0]), "r"(b[1]));
}

// ================= reductions =================
__device__ __forceinline__ void block_reduce_add(float v, double scale) {
    __shared__ float red[256];
    int t = threadIdx.y * blockDim.x + threadIdx.x;
    red[t] = v;
    __syncthreads();
    for (int s = 128; s > 0; s >>= 1) {
        if (t < s) red[t] += red[t + s];
        __syncthreads();
    }
    if (t == 0) atomicAdd(&d_loss, scale * (double)red[0]);
}

__global__ void k_zero() { d_loss = 0.0; }
__global__ void k_final(float* out) { out[0] = (float)d_loss; }

// ================= composite / hole+valid / perc =================
__global__ void k_comp(const float* __restrict__ igt, const float* __restrict__ iout,
                       const float* __restrict__ mask) {
    const int HW2 = 512 * 512;
    const int n = 2 * 3 * HW2;
    int idx = blockIdx.x * blockDim.x + threadIdx.x;
    if (idx >= n) return;
    int b = idx / (3 * HW2);
    int p = idx % HW2;
    bool m = (mask[b * HW2 + p] != 0.0f);
    d_compbuf[idx] = m ? igt[idx] : iout[idx];
}

__global__ void k_holevalid(const float* __restrict__ igt, const float* __restrict__ iout,
                            const float* __restrict__ mask) {
    const int HW2 = 512 * 512;
    const int n = 2 * 3 * HW2;
    float s = 0.f;
    for (int idx = blockIdx.x * blockDim.x + threadIdx.x; idx < n;
         idx += gridDim.x * blockDim.x) {
        int b = idx / (3 * HW2);
        int p = idx % HW2;
        bool m = (mask[b * HW2 + p] != 0.0f);
        float d = fabsf(iout[idx] - igt[idx]);
        s += d * (m ? 1.0f : 2.0f);
    }
    block_reduce_add(s, 1.0 / (3.0 * 512.0 * 512.0 * 2.0));
}

__global__ void k_perc(const float* __restrict__ po, const float* __restrict__ pg,
                       const float* __restrict__ pc, int n, double scale) {
    float s = 0.f;
    for (int i = blockIdx.x * blockDim.x + threadIdx.x; i < n;
         i += gridDim.x * blockDim.x) {
        float g = pg[i];
        s += fabsf(po[i] - g) + fabsf(pc[i] - g);
    }
    block_reduce_add(s, scale);
}

// ========== fused weight transform: all 6 layers in ONE launch ==========
// OIHW fp32 -> [shift][cout][cin] bf16 at per-layer offset.
__global__ void k_wt_all(const float* __restrict__ w1, const float* __restrict__ w2,
                         const float* __restrict__ w3, const float* __restrict__ w4,
                         const float* __restrict__ w5, const float* __restrict__ w6,
                         __nv_bfloat16* __restrict__ dst) {
    const int CO[6] = {64, 128, 128, 256, 256, 256};
    const int CI[6] = {64, 64, 128, 128, 256, 256};
    const size_t OFF[6] = {0, 36864, 110592, 258048, 552960, 1142784};
    const float* ws[6] = {w1, w2, w3, w4, w5, w6};

    const int l = blockIdx.y;
    const int Cout = CO[l], Cin = CI[l];
    const int n = 9 * Cout * Cin;
    int idx = blockIdx.x * blockDim.x + threadIdx.x;
    if (idx >= n) return;
    int sh = idx / (Cout * Cin);
    int r = idx - sh * (Cout * Cin);
    int co = r / Cin, ci = r - co * Cin;
    dst[OFF[l] + idx] = __float2bfloat16(ws[l][((size_t)co * Cin + ci) * 9 + sh]);
}

// ================= layer0: 3->64 FFMA2 conv, NCHW fp32 -> NHWC bf16 ===========
__global__ __launch_bounds__(256, 2) void k_conv0(
    const float* __restrict__ in, __nv_bfloat16* __restrict__ out,
    const float* __restrict__ wt, const float* __restrict__ bs) {
    const int HW = 512;
    __shared__ __align__(16) float sIn[3][34 * 34];
    __shared__ __align__(16) float sW[3][9][8];

    const int tx = threadIdx.x, ty = threadIdx.y;
    const int tid = ty * 32 + tx;
    const int b = blockIdx.z >> 3;
    const int c0 = (blockIdx.z & 7) * 8;
    const int x0 = blockIdx.x * 32, y0 = blockIdx.y * 32;

    const float* inB = in + (size_t)b * 3 * HW * HW;
    for (int i = tid; i < 3 * 1156; i += 256) {
        int kc = i / 1156;
        int r = i - kc * 1156;
        int py = r / 34, px = r - py * 34;
        int gy = y0 - 1 + py, gx = x0 - 1 + px;
        float v = 0.f;
        if ((unsigned)gy < (unsigned)HW && (unsigned)gx < (unsigned)HW)
            v = inB[(size_t)kc * HW * HW + (size_t)gy * HW + gx];
        sIn[kc][r] = v;
    }
    for (int i = tid; i < 3 * 72; i += 256) {
        int kc = i / 72;
        int r = i - kc * 72;
        int k = r >> 3, f = r & 7;
        sW[kc][k][f] = wt[(size_t)(c0 + f) * 27 + kc * 9 + k];
    }
    __syncthreads();

    unsigned long long acc[4][4];
    #pragma unroll
    for (int r = 0; r < 4; ++r)
        #pragma unroll
        for (int p = 0; p < 4; ++p) acc[r][p] = 0ull;

    #pragma unroll
    for (int kc = 0; kc < 3; ++kc) {
        unsigned long long ip[6][3];
        #pragma unroll
        for (int r = 0; r < 6; ++r)
            #pragma unroll
            for (int c = 0; c < 3; ++c)
                ip[r][c] = pk2(sIn[kc][(4 * ty + r) * 34 + tx + c]);
        #pragma unroll
        for (int p = 0; p < 4; ++p) {
            #pragma unroll
            for (int k = 0; k < 9; ++k) {
                unsigned long long w = *(const unsigned long long*)&sW[kc][k][2 * p];
                const int ky = k / 3, kx = k - 3 * (k / 3);
                #pragma unroll
                for (int r = 0; r < 4; ++r)
                    fma2(acc[r][p], ip[r + ky][kx], w);
            }
        }
    }

    #pragma unroll
    for (int r = 0; r < 4; ++r) {
        uint32_t pk[4];
        #pragma unroll
        for (int p = 0; p < 4; ++p) {
            float lo, hi;
            upk2(acc[r][p], lo, hi);
            lo = fmaxf(lo + bs[c0 + 2 * p], 0.f);
            hi = fmaxf(hi + bs[c0 + 2 * p + 1], 0.f);
            uint32_t l16 = (uint32_t)__bfloat16_as_ushort(__float2bfloat16(lo));
            uint32_t h16 = (uint32_t)__bfloat16_as_ushort(__float2bfloat16(hi));
            pk[p] = l16 | (h16 << 16);
        }
        int y = y0 + 4 * ty + r, x = x0 + tx;
        size_t p = (size_t)b * HW * HW + (size_t)y * HW + x;
        *(uint4*)(out + p * 64 + c0) = make_uint4(pk[0], pk[1], pk[2], pk[3]);
    }
}

// ========= warp-MMA implicit-GEMM 3x3 conv, B-halo reuse across kx ==========
// Loop 3 ky x cin-chunks. One (NT+2)-pixel halo B tile serves all 3 kx shifts
// (smem row offset +kx); A holds the 3 kx weight slices.
template <int MT, int NT>
__global__ __launch_bounds__(256) void k_convmma(
    const __nv_bfloat16* __restrict__ in, __nv_bfloat16* __restrict__ out,
    const __nv_bfloat16* __restrict__ wt, const float* __restrict__ bs,
    int Cin, int Cout, int H, int W) {
    constexpr int WM = (MT == 128) ? 2 : 1;
    constexpr int STR = 72;                   // smem row stride (bf16)
    constexpr int OSTR = MT + 8;
    extern __shared__ __align__(16) char dsm[];
    __nv_bfloat16* st = (__nv_bfloat16*)dsm;

    const int tid = threadIdx.x;
    const int lane = tid & 31, wid = tid >> 5;
    const int warpM = wid % WM, warpN = wid / WM;

    const int tileP = blockIdx.x * NT;
    const int b = tileP / (H * W);
    const int rem = tileP - b * H * W;
    const int y = rem / W, x0 = rem - (rem / W) * W;
    const int coutBase = blockIdx.y * MT;

    const uint32_t sAu = s2u(st);                       // 3*MT rows
    const uint32_t sBu = sAu + 3 * MT * STR * 2;        // NT+2 rows

    float acc[4][4][4];
    #pragma unroll
    for (int mi = 0; mi < 4; ++mi)
        #pragma unroll
        for (int nj = 0; nj < 4; ++nj)
            #pragma unroll
            for (int e = 0; e < 4; ++e) acc[mi][nj][e] = 0.f;

    const int nCh = Cin >> 6;

    for (int ky = 0; ky < 3; ++ky) {
        const int ys = y + ky - 1;
        const bool rowv = (unsigned)ys < (unsigned)H;
        const __nv_bfloat16* inrow = in + ((size_t)(b * H + ys) * W) * Cin;

        for (int ch = 0; ch < nCh; ++ch) {
            const int c0 = ch * 64;
            __syncthreads();   // previous iteration's fragment readers done
            // A: 3 kx weight slices, MT rows each
            for (int o = tid; o < 3 * MT * 8; o += 256) {
                int kx = o / (MT * 8);
                int r = o - kx * (MT * 8);
                int row = r >> 3, seg = r & 7;
                const __nv_bfloat16* wsh =
                    wt + ((size_t)(ky * 3 + kx) * Cout + coutBase + row) * Cin;
                cp_async16(sAu + ((kx * MT + row) * STR + seg * 8) * 2,
                           wsh + c0 + seg * 8, true);
            }
            // B: NT+2 halo pixel rows (xs = x0-1+j), zfill OOB
            for (int o = tid; o < (NT + 2) * 8; o += 256) {
                int j = o >> 3, seg = o & 7;
                int xs = x0 - 1 + j;
                bool v = rowv && (unsigned)xs < (unsigned)W;
                cp_async16(sBu + (j * STR + seg * 8) * 2,
                           inrow + (size_t)xs * Cin + c0 + seg * 8, v);
            }
            cp_commit();
            cp_wait<0>();
            __syncthreads();

            #pragma unroll
            for (int kx = 0; kx < 3; ++kx) {
                #pragma unroll
                for (int ks = 0; ks < 4; ++ks) {
                    const int kk = ks * 16;
                    uint32_t af[4][4];
                    #pragma unroll
                    for (int mi = 0; mi < 4; ++mi) {
                        int row = kx * MT + warpM * 64 + mi * 16 + (lane & 7) +
                                  ((lane >> 3) & 1) * 8;
                        int col = kk + (lane >> 4) * 8;
                        ldsm4(af[mi][0], af[mi][1], af[mi][2], af[mi][3],
                              sAu + (row * STR + col) * 2);
                    }
                    uint32_t bf[4][2];
                    #pragma unroll
                    for (int pj = 0; pj < 2; ++pj) {
                        int row = warpN * 32 + pj * 16 + (lane & 7) +
                                  (lane >> 4) * 8 + kx;
                        int col = kk + ((lane >> 3) & 1) * 8;
                        uint32_t r0, r1, r2, r3;
                        ldsm4(r0, r1, r2, r3, sBu + (row * STR + col) * 2);
                        bf[2 * pj][0] = r0; bf[2 * pj][1] = r1;
                        bf[2 * pj + 1][0] = r2; bf[2 * pj + 1][1] = r3;
                    }
                    #pragma unroll
                    for (int mi = 0; mi < 4; ++mi)
                        #pragma unroll
                        for (int nj = 0; nj < 4; ++nj)
                            mma16816(acc[mi][nj], af[mi], bf[nj]);
                }
            }
        }
    }

    // ---- epilogue: bias + relu -> smem [pixel][cout] -> coalesced NHWC stores
    __syncthreads();
    __nv_bfloat16* ob = (__nv_bfloat16*)dsm;
    #pragma unroll
    for (int mi = 0; mi < 4; ++mi) {
        int m = warpM * 64 + mi * 16 + (lane >> 2);
        float bv0 = bs[coutBase + m];
        float bv1 = bs[coutBase + m + 8];
        #pragma unroll
        for (int nj = 0; nj < 4; ++nj) {
            int n = warpN * 32 + nj * 8 + (lane & 3) * 2;
            float* c = acc[mi][nj];
            ob[n * OSTR + m]           = __float2bfloat16(fmaxf(c[0] + bv0, 0.f));
            ob[(n + 1) * OSTR + m]     = __float2bfloat16(fmaxf(c[1] + bv0, 0.f));
            ob[n * OSTR + m + 8]       = __float2bfloat16(fmaxf(c[2] + bv1, 0.f));
            ob[(n + 1) * OSTR + m + 8] = __float2bfloat16(fmaxf(c[3] + bv1, 0.f));
        }
    }
    __syncthreads();
    constexpr int HALF = MT / 2;
    for (int o = tid; o < NT * HALF; o += 256) {
        int row = o / HALF, cp = o - row * HALF;
        uint32_t v = *(const uint32_t*)&ob[row * OSTR + cp * 2];
        *(uint32_t*)&out[(size_t)(tileP + row) * Cout + coutBase + cp * 2] = v;
    }
}

// ================= pool: NHWC bf16 -> NCHW fp32 (+ optional NHWC bf16) ========
__global__ __launch_bounds__(256) void k_poolT(
    const __nv_bfloat16* __restrict__ in, float* __restrict__ outN,
    __nv_bfloat16* __restrict__ outT, int C, int Ho, int Wo) {
    __shared__ float s[32][65];
    const int tid = threadIdx.x;
    const int p0 = blockIdx.x * 32;
    const int c0 = blockIdx.y * 64;
    const int b = blockIdx.z;
    const int W = Wo * 2;
    const __nv_bfloat16* inb = in + (size_t)b * (Ho * 2) * W * C;

    #pragma unroll
    for (int e = 0; e < 8; ++e) {
        int elem = tid + 256 * e;
        int c = elem & 63, pix = elem >> 6;
        int p = p0 + pix;
        int yy = p / Wo, xx = p - yy * Wo;
        const __nv_bfloat16* q = inb + ((size_t)(2 * yy) * W + 2 * xx) * C + c0 + c;
        float v0 = __bfloat162float(q[0]);
        float v1 = __bfloat162float(q[C]);
        float v2 = __bfloat162float(q[(size_t)W * C]);
        float v3 = __bfloat162float(q[(size_t)W * C + C]);
        float m = fmaxf(fmaxf(v0, v1), fmaxf(v2, v3));
        s[pix][c] = m;
        if (outT)
            outT[((size_t)b * Ho * Wo + p) * C + c0 + c] = __float2bfloat16(m);
    }
    __syncthreads();
    #pragma unroll
    for (int e = 0; e < 8; ++e) {
        int elem = tid + 256 * e;
        int pix = elem & 31, c = elem >> 5;
        outN[((size_t)(b * C + c0 + c)) * Ho * Wo + p0 + pix] = s[pix][c];
    }
}

// ================= tensor-core style Gram kernel =============================
__global__ __launch_bounds__(256) void k_gram_mma(
    const float* __restrict__ g, const float* __restrict__ a0,
    const float* __restrict__ a1, int Wd, int nT, double scale) {
    __shared__ __align__(16) __nv_bfloat16 sT[3][2][64][24];
    const int tid = threadIdx.x;
    const int lane = tid & 31, wid = tid >> 5;
    const int warpM = wid & 3, warpN = wid >> 2;

    int p = blockIdx.x, it = 0;
    while (p >= nT - it) { p -= nT - it; ++it; }
    const int jt = it + p;
    const int w0 = it * 64, v0 = jt * 64;

    const size_t base = (size_t)blockIdx.y * Wd * Wd;
    const float* mats[3] = {g, a0, a1};

    float acc[3][4][4];
    #pragma unroll
    for (int m = 0; m < 3; ++m)
        #pragma unroll
        for (int nj = 0; nj < 4; ++nj)
            #pragma unroll
            for (int e = 0; e < 4; ++e) acc[m][nj][e] = 0.f;

    const int nChunks = Wd >> 4;
    for (int kb = 0; kb < nChunks; ++kb) {
        __syncthreads();
        for (int o = tid; o < 6144; o += 256) {
            int mat = o / 2048;
            int r = o - mat * 2048;
            int sl = r >> 10;
            int e = r & 1023;
            int h = e >> 6, w = e & 63;
            int col0 = sl ? v0 : w0;
            float f = mats[mat][base + (size_t)(kb * 16 + h) * Wd + col0 + w];
            sT[mat][sl][w][h] = __float2bfloat16(f);
        }
        __syncthreads();

        #pragma unroll
        for (int mat = 0; mat < 3; ++mat) {
            uint32_t af[4];
            {
                int row = warpM * 16 + (lane & 7) + ((lane >> 3) & 1) * 8;
                int col = (lane >> 4) * 8;
                ldsm4(af[0], af[1], af[2], af[3], s2u(&sT[mat][0][row][col]));
            }
            uint32_t bf[4][2];
            #pragma unroll
            for (int pj = 0; pj < 2; ++pj) {
                int row = warpN * 32 + pj * 16 + (lane & 7) + (lane >> 4) * 8;
                int col = ((lane >> 3) & 1) * 8;
                uint32_t r0, r1, r2, r3;
                ldsm4(r0, r1, r2, r3, s2u(&sT[mat][1][row][col]));
                bf[2 * pj][0] = r0; bf[2 * pj][1] = r1;
                bf[2 * pj + 1][0] = r2; bf[2 * pj + 1][1] = r3;
            }
            #pragma unroll
            for (int nj = 0; nj < 4; ++nj)
                mma16816(acc[mat][nj], af, bf[nj]);
        }
    }

    float sum = 0.f;
    #pragma unroll
    for (int nj = 0; nj < 4; ++nj) {
        #pragma unroll
        for (int e = 0; e < 4; ++e) {
            int w = w0 + warpM * 16 + (lane >> 2) + (e >= 2 ? 8 : 0);
            int v = v0 + warpN * 32 + nj * 8 + (lane & 3) * 2 + (e & 1);
            float wgt = (jt > it) ? 2.f : (v > w ? 2.f : (v == w ? 1.f : 0.f));
            float gg = acc[0][nj][e];
            sum += wgt * (fabsf(acc[1][nj][e] - gg) + fabsf(acc[2][nj][e] - gg));
        }
    }
    block_reduce_add(sum, scale);
}

// ================= host orchestration =================
extern "C" void kernel_launch(void* const* d_in, const int* in_sizes, int n_in,
                              void* d_out, int out_size) {
    const float* igt  = (const float*)d_in[0];
    const float* iout = (const float*)d_in[1];
    const float* mask = (const float*)d_in[2];
    const float* W[7];
    const float* Bi[7];
    for (int i = 0; i < 7; ++i) {
        W[i]  = (const float*)d_in[3 + 2 * i];
        Bi[i] = (const float*)d_in[4 + 2 * i];
    }

    __nv_bfloat16 *tA, *tB, *wtb;
    float *comp, *p1, *p2, *p3;
    cudaGetSymbolAddress((void**)&tA, d_tA);
    cudaGetSymbolAddress((void**)&tB, d_tB);
    cudaGetSymbolAddress((void**)&wtb, d_wtb);
    cudaGetSymbolAddress((void**)&comp, d_compbuf);
    cudaGetSymbolAddress((void**)&p1, d_p1);
    cudaGetSymbolAddress((void**)&p2, d_p2);
    cudaGetSymbolAddress((void**)&p3, d_p3);

    const size_t s1 = 2ull * 64 * 256 * 256;
    const size_t s2 = 2ull * 128 * 128 * 128;
    const size_t s3 = 2ull * 256 * 64 * 64;

    const size_t wo[6] = {0, 36864, 110592, 258048, 552960, 1142784};

    // dynamic smem: (3*MT + NT + 2) * 72 * 2 bytes
    const int SM1 = (3 * 64 + 256 + 2) * 72 * 2;    // 64800
    const int SM2 = (3 * 128 + 128 + 2) * 72 * 2;   // 74016
    cudaFuncSetAttribute(k_convmma<64, 256>,
                         cudaFuncAttributeMaxDynamicSharedMemorySize, SM1);
    cudaFuncSetAttribute(k_convmma<128, 128>,
                         cudaFuncAttributeMaxDynamicSharedMemorySize, SM2);

    // launch order: #6 (1-based, after -s 5) = k_convmma l1 -> ncu captures it
    k_zero<<<1, 1>>>();                                               // 1
    k_wt_all<<<dim3(2304, 6), 256>>>(W[1], W[2], W[3], W[4], W[5], W[6], wtb);  // 2
    const int nC = 2 * 3 * 512 * 512;
    k_comp<<<(nC + 255) / 256, 256>>>(igt, iout, mask);               // 3
    k_holevalid<<<1024, 256>>>(igt, iout, mask);                      // 4

    for (int img = 0; img < 3; ++img) {
        const float* src = (img == 0) ? iout : (img == 1) ? igt : comp;
        k_conv0<<<dim3(16, 16, 16), dim3(32, 8)>>>(src, tA, W[0], Bi[0]);  // 5
        k_convmma<64, 256><<<dim3(2048, 1), 256, SM1>>>(tA, tB, wtb + wo[0], Bi[1],
                                                        64, 64, 512, 512); // 6 <- ncu
        k_poolT<<<dim3(2048, 1, 2), 256>>>(tB, p1 + img * s1, tA, 64, 256, 256);
        k_convmma<128, 128><<<dim3(1024, 1), 256, SM2>>>(tA, tB, wtb + wo[1], Bi[2],
                                                         64, 128, 256, 256);
        k_convmma<128, 128><<<dim3(1024, 1), 256, SM2>>>(tB, tA, wtb + wo[2], Bi[3],
                                                         128, 128, 256, 256);
        k_poolT<<<dim3(512, 2, 2), 256>>>(tA, p2 + img * s2, tB, 128, 128, 128);
        k_convmma<128, 128><<<dim3(256, 2), 256, SM2>>>(tB, tA, wtb + wo[3], Bi[4],
                                                        128, 256, 128, 128);
        k_convmma<128, 128><<<dim3(256, 2), 256, SM2>>>(tA, tB, wtb + wo[4], Bi[5],
                                                        256, 256, 128, 128);
        k_convmma<128, 128><<<dim3(256, 2), 256, SM2>>>(tB, tA, wtb + wo[5], Bi[6],
                                                        256, 256, 128, 128);
        k_poolT<<<dim3(128, 4, 2), 256>>>(tA, p3 + img * s3, (__nv_bfloat16*)nullptr,
                                          256, 64, 64);
    }

    const double invNigt = 1.0 / 8388608.0;
    k_perc<<<1024, 256>>>(p1, p1 + s1, p1 + 2 * s1, (int)s1, invNigt);
    k_perc<<<1024, 256>>>(p2, p2 + s2, p2 + 2 * s2, (int)s2, invNigt);
    k_perc<<<1024, 256>>>(p3, p3 + s3, p3 + 2 * s3, (int)s3, invNigt);

    {
        double sc = 1.0 / (64.0 * 256.0 * 256.0) / (64.0 * 64.0);
        k_gram_mma<<<dim3(10, 2 * 64), 256>>>(p1 + s1, p1, p1 + 2 * s1, 256, 4, sc);
    }
    {
        double sc = 1.0 / (128.0 * 128.0 * 128.0) / (128.0 * 128.0);
        k_gram_mma<<<dim3(3, 2 * 128), 256>>>(p2 + s2, p2, p2 + 2 * s2, 128, 2, sc);
    }
    {
        double sc = 1.0 / (256.0 * 64.0 * 64.0) / (256.0 * 256.0);
        k_gram_mma<<<dim3(1, 2 * 256), 256>>>(p3 + s3, p3, p3 + 2 * s3, 64, 1, sc);
    }

    k_final<<<1, 1>>>((float*)d_out);
}

// round 10
// speedup vs baseline: 15.6450x; 1.1001x over previous
#include <cuda_runtime.h>
#include <cuda_bf16.h>
#include <math.h>
#include <stdint.h>

// ================= scratch (device globals; allocation-free) =================
__device__ __nv_bfloat16 d_tA[3][33554432];        // per-image NHWC ping
__device__ __nv_bfloat16 d_tB[3][33554432];        // per-image NHWC pong
__device__ __nv_bfloat16 d_wtb[1732608];           // [shift][cout][cin] bf16 weights
__device__ float d_compbuf[2 * 3 * 512 * 512];
__device__ float d_p1[3 * 2 * 64 * 256 * 256];
__device__ float d_p2[3 * 2 * 128 * 128 * 128];
__device__ float d_p3[3 * 2 * 256 * 64 * 64];
__device__ double d_loss;

// ================= helpers =================
__device__ __forceinline__ uint32_t s2u(const void* p) {
    return (uint32_t)__cvta_generic_to_shared(p);
}
__device__ __forceinline__ void cp_async16(uint32_t dst, const void* src, bool valid) {
    int sz = valid ? 16 : 0;
    asm volatile("cp.async.cg.shared.global [%0], [%1], 16, %2;\n"
                 :: "r"(dst), "l"(src), "r"(sz));
}
__device__ __forceinline__ void cp_commit() {
    asm volatile("cp.async.commit_group;\n");
}
template <int N>
__device__ __forceinline__ void cp_wait() {
    asm volatile("cp.async.wait_group %0;\n" :: "n"(N));
}

// f32x2 (layer0)
__device__ __forceinline__ unsigned long long pk2(float v) {
    unsigned long long r;
    asm("mov.b64 %0, {%1, %1};" : "=l"(r) : "r"(__float_as_uint(v)));
    return r;
}
__device__ __forceinline__ void fma2(unsigned long long& d, unsigned long long a,
                                     unsigned long long b) {
    asm("fma.rn.f32x2 %0, %1, %2, %0;" : "+l"(d) : "l"(a), "l"(b));
}
__device__ __forceinline__ void upk2(unsigned long long v, float& lo, float& hi) {
    unsigned ulo, uhi;
    asm("mov.b64 {%0, %1}, %2;" : "=r"(ulo), "=r"(uhi) : "l"(v));
    lo = __uint_as_float(ulo);
    hi = __uint_as_float(uhi);
}

// warp MMA primitives (sm_80+, legal on base sm_103 target)
__device__ __forceinline__ void ldsm4(uint32_t& r0, uint32_t& r1, uint32_t& r2,
                                      uint32_t& r3, uint32_t addr) {
    asm volatile("ldmatrix.sync.aligned.m8n8.x4.shared.b16 {%0,%1,%2,%3}, [%4];"
                 : "=r"(r0), "=r"(r1), "=r"(r2), "=r"(r3) : "r"(addr));
}
__device__ __forceinline__ void mma16816(float* c, const uint32_t* a,
                                         const uint32_t* b) {
    asm volatile(
        "mma.sync.aligned.m16n8k16.row.col.f32.bf16.bf16.f32 "
        "{%0,%1,%2,%3}, {%4,%5,%6,%7}, {%8,%9}, {%0,%1,%2,%3};"
        : "+f"(c[0]), "+f"(c[1]), "+f"(c[2]), "+f"(c[3])
        : "r"(a[0]), "r"(a[1]), "r"(a[2]), "r"(a[3]), "r"(b[0]), "r"(b[1]));
}

// ================= reductions =================
__device__ __forceinline__ void block_reduce_add(float v, double scale) {
    __shared__ float red[256];
    int t = threadIdx.y * blockDim.x + threadIdx.x;
    red[t] = v;
    __syncthreads();
    for (int s = 128; s > 0; s >>= 1) {
        if (t < s) red[t] += red[t + s];
        __syncthreads();
    }
    if (t == 0) atomicAdd(&d_loss, scale * (double)red[0]);
}

__global__ void k_zero() { d_loss = 0.0; }
__global__ void k_final(float* out) { out[0] = (float)d_loss; }

// ================= composite / hole+valid / perc =================
__global__ void k_comp(const float* __restrict__ igt, const float* __restrict__ iout,
                       const float* __restrict__ mask) {
    const int HW2 = 512 * 512;
    const int n = 2 * 3 * HW2;
    int idx = blockIdx.x * blockDim.x + threadIdx.x;
    if (idx >= n) return;
    int b = idx / (3 * HW2);
    int p = idx % HW2;
    bool m = (mask[b * HW2 + p] != 0.0f);
    d_compbuf[idx] = m ? igt[idx] : iout[idx];
}

__global__ void k_holevalid(const float* __restrict__ igt, const float* __restrict__ iout,
                            const float* __restrict__ mask) {
    const int HW2 = 512 * 512;
    const int n = 2 * 3 * HW2;
    float s = 0.f;
    for (int idx = blockIdx.x * blockDim.x + threadIdx.x; idx < n;
         idx += gridDim.x * blockDim.x) {
        int b = idx / (3 * HW2);
        int p = idx % HW2;
        bool m = (mask[b * HW2 + p] != 0.0f);
        float d = fabsf(iout[idx] - igt[idx]);
        s += d * (m ? 1.0f : 2.0f);
    }
    block_reduce_add(s, 1.0 / (3.0 * 512.0 * 512.0 * 2.0));
}

__global__ void k_perc(const float* __restrict__ po, const float* __restrict__ pg,
                       const float* __restrict__ pc, int n, double scale) {
    float s = 0.f;
    for (int i = blockIdx.x * blockDim.x + threadIdx.x; i < n;
         i += gridDim.x * blockDim.x) {
        float g = pg[i];
        s += fabsf(po[i] - g) + fabsf(pc[i] - g);
    }
    block_reduce_add(s, scale);
}

// ========== fused weight transform: all 6 layers in ONE launch ==========
__global__ void k_wt_all(const float* __restrict__ w1, const float* __restrict__ w2,
                         const float* __restrict__ w3, const float* __restrict__ w4,
                         const float* __restrict__ w5, const float* __restrict__ w6,
                         __nv_bfloat16* __restrict__ dst) {
    const int CO[6] = {64, 128, 128, 256, 256, 256};
    const int CI[6] = {64, 64, 128, 128, 256, 256};
    const size_t OFF[6] = {0, 36864, 110592, 258048, 552960, 1142784};
    const float* ws[6] = {w1, w2, w3, w4, w5, w6};

    const int l = blockIdx.y;
    const int Cout = CO[l], Cin = CI[l];
    const int n = 9 * Cout * Cin;
    int idx = blockIdx.x * blockDim.x + threadIdx.x;
    if (idx >= n) return;
    int sh = idx / (Cout * Cin);
    int r = idx - sh * (Cout * Cin);
    int co = r / Cin, ci = r - co * Cin;
    dst[OFF[l] + idx] = __float2bfloat16(ws[l][((size_t)co * Cin + ci) * 9 + sh]);
}

// ================= layer0: 3->64 FFMA2 conv, NCHW fp32 -> NHWC bf16 ===========
__global__ __launch_bounds__(256, 2) void k_conv0(
    const float* __restrict__ in, __nv_bfloat16* __restrict__ out,
    const float* __restrict__ wt, const float* __restrict__ bs) {
    const int HW = 512;
    __shared__ __align__(16) float sIn[3][34 * 34];
    __shared__ __align__(16) float sW[3][9][8];

    const int tx = threadIdx.x, ty = threadIdx.y;
    const int tid = ty * 32 + tx;
    const int b = blockIdx.z >> 3;
    const int c0 = (blockIdx.z & 7) * 8;
    const int x0 = blockIdx.x * 32, y0 = blockIdx.y * 32;

    const float* inB = in + (size_t)b * 3 * HW * HW;
    for (int i = tid; i < 3 * 1156; i += 256) {
        int kc = i / 1156;
        int r = i - kc * 1156;
        int py = r / 34, px = r - py * 34;
        int gy = y0 - 1 + py, gx = x0 - 1 + px;
        float v = 0.f;
        if ((unsigned)gy < (unsigned)HW && (unsigned)gx < (unsigned)HW)
            v = inB[(size_t)kc * HW * HW + (size_t)gy * HW + gx];
        sIn[kc][r] = v;
    }
    for (int i = tid; i < 3 * 72; i += 256) {
        int kc = i / 72;
        int r = i - kc * 72;
        int k = r >> 3, f = r & 7;
        sW[kc][k][f] = wt[(size_t)(c0 + f) * 27 + kc * 9 + k];
    }
    __syncthreads();

    unsigned long long acc[4][4];
    #pragma unroll
    for (int r = 0; r < 4; ++r)
        #pragma unroll
        for (int p = 0; p < 4; ++p) acc[r][p] = 0ull;

    #pragma unroll
    for (int kc = 0; kc < 3; ++kc) {
        unsigned long long ip[6][3];
        #pragma unroll
        for (int r = 0; r < 6; ++r)
            #pragma unroll
            for (int c = 0; c < 3; ++c)
                ip[r][c] = pk2(sIn[kc][(4 * ty + r) * 34 + tx + c]);
        #pragma unroll
        for (int p = 0; p < 4; ++p) {
            #pragma unroll
            for (int k = 0; k < 9; ++k) {
                unsigned long long w = *(const unsigned long long*)&sW[kc][k][2 * p];
                const int ky = k / 3, kx = k - 3 * (k / 3);
                #pragma unroll
                for (int r = 0; r < 4; ++r)
                    fma2(acc[r][p], ip[r + ky][kx], w);
            }
        }
    }

    #pragma unroll
    for (int r = 0; r < 4; ++r) {
        uint32_t pk[4];
        #pragma unroll
        for (int p = 0; p < 4; ++p) {
            float lo, hi;
            upk2(acc[r][p], lo, hi);
            lo = fmaxf(lo + bs[c0 + 2 * p], 0.f);
            hi = fmaxf(hi + bs[c0 + 2 * p + 1], 0.f);
            uint32_t l16 = (uint32_t)__bfloat16_as_ushort(__float2bfloat16(lo));
            uint32_t h16 = (uint32_t)__bfloat16_as_ushort(__float2bfloat16(hi));
            pk[p] = l16 | (h16 << 16);
        }
        int y = y0 + 4 * ty + r, x = x0 + tx;
        size_t p = (size_t)b * HW * HW + (size_t)y * HW + x;
        *(uint4*)(out + p * 64 + c0) = make_uint4(pk[0], pk[1], pk[2], pk[3]);
    }
}

// ========= warp-MMA implicit-GEMM 3x3 conv, B-halo reuse across kx ==========
template <int MT, int NT>
__global__ __launch_bounds__(256) void k_convmma(
    const __nv_bfloat16* __restrict__ in, __nv_bfloat16* __restrict__ out,
    const __nv_bfloat16* __restrict__ wt, const float* __restrict__ bs,
    int Cin, int Cout, int H, int W) {
    constexpr int WM = (MT == 128) ? 2 : 1;
    constexpr int STR = 72;                   // smem row stride (bf16)
    constexpr int OSTR = MT + 8;
    extern __shared__ __align__(16) char dsm[];
    __nv_bfloat16* st = (__nv_bfloat16*)dsm;

    const int tid = threadIdx.x;
    const int lane = tid & 31, wid = tid >> 5;
    const int warpM = wid % WM, warpN = wid / WM;

    const int tileP = blockIdx.x * NT;
    const int b = tileP / (H * W);
    const int rem = tileP - b * H * W;
    const int y = rem / W, x0 = rem - (rem / W) * W;
    const int coutBase = blockIdx.y * MT;

    const uint32_t sAu = s2u(st);                       // 3*MT rows
    const uint32_t sBu = sAu + 3 * MT * STR * 2;        // NT+2 rows

    float acc[4][4][4];
    #pragma unroll
    for (int mi = 0; mi < 4; ++mi)
        #pragma unroll
        for (int nj = 0; nj < 4; ++nj)
            #pragma unroll
            for (int e = 0; e < 4; ++e) acc[mi][nj][e] = 0.f;

    const int nCh = Cin >> 6;

    for (int ky = 0; ky < 3; ++ky) {
        const int ys = y + ky - 1;
        const bool rowv = (unsigned)ys < (unsigned)H;
        const __nv_bfloat16* inrow = in + ((size_t)(b * H + ys) * W) * Cin;

        for (int ch = 0; ch < nCh; ++ch) {
            const int c0 = ch * 64;
            __syncthreads();
            for (int o = tid; o < 3 * MT * 8; o += 256) {
                int kx = o / (MT * 8);
                int r = o - kx * (MT * 8);
                int row = r >> 3, seg = r & 7;
                const __nv_bfloat16* wsh =
                    wt + ((size_t)(ky * 3 + kx) * Cout + coutBase + row) * Cin;
                cp_async16(sAu + ((kx * MT + row) * STR + seg * 8) * 2,
                           wsh + c0 + seg * 8, true);
            }
            for (int o = tid; o < (NT + 2) * 8; o += 256) {
                int j = o >> 3, seg = o & 7;
                int xs = x0 - 1 + j;
                bool v = rowv && (unsigned)xs < (unsigned)W;
                cp_async16(sBu + (j * STR + seg * 8) * 2,
                           inrow + (size_t)xs * Cin + c0 + seg * 8, v);
            }
            cp_commit();
            cp_wait<0>();
            __syncthreads();

            #pragma unroll
            for (int kx = 0; kx < 3; ++kx) {
                #pragma unroll
                for (int ks = 0; ks < 4; ++ks) {
                    const int kk = ks * 16;
                    uint32_t af[4][4];
                    #pragma unroll
                    for (int mi = 0; mi < 4; ++mi) {
                        int row = kx * MT + warpM * 64 + mi * 16 + (lane & 7) +
                                  ((lane >> 3) & 1) * 8;
                        int col = kk + (lane >> 4) * 8;
                        ldsm4(af[mi][0], af[mi][1], af[mi][2], af[mi][3],
                              sAu + (row * STR + col) * 2);
                    }
                    uint32_t bf[4][2];
                    #pragma unroll
                    for (int pj = 0; pj < 2; ++pj) {
                        int row = warpN * 32 + pj * 16 + (lane & 7) +
                                  (lane >> 4) * 8 + kx;
                        int col = kk + ((lane >> 3) & 1) * 8;
                        uint32_t r0, r1, r2, r3;
                        ldsm4(r0, r1, r2, r3, sBu + (row * STR + col) * 2);
                        bf[2 * pj][0] = r0; bf[2 * pj][1] = r1;
                        bf[2 * pj + 1][0] = r2; bf[2 * pj + 1][1] = r3;
                    }
                    #pragma unroll
                    for (int mi = 0; mi < 4; ++mi)
                        #pragma unroll
                        for (int nj = 0; nj < 4; ++nj)
                            mma16816(acc[mi][nj], af[mi], bf[nj]);
                }
            }
        }
    }

    __syncthreads();
    __nv_bfloat16* ob = (__nv_bfloat16*)dsm;
    #pragma unroll
    for (int mi = 0; mi < 4; ++mi) {
        int m = warpM * 64 + mi * 16 + (lane >> 2);
        float bv0 = bs[coutBase + m];
        float bv1 = bs[coutBase + m + 8];
        #pragma unroll
        for (int nj = 0; nj < 4; ++nj) {
            int n = warpN * 32 + nj * 8 + (lane & 3) * 2;
            float* c = acc[mi][nj];
            ob[n * OSTR + m]           = __float2bfloat16(fmaxf(c[0] + bv0, 0.f));
            ob[(n + 1) * OSTR + m]     = __float2bfloat16(fmaxf(c[1] + bv0, 0.f));
            ob[n * OSTR + m + 8]       = __float2bfloat16(fmaxf(c[2] + bv1, 0.f));
            ob[(n + 1) * OSTR + m + 8] = __float2bfloat16(fmaxf(c[3] + bv1, 0.f));
        }
    }
    __syncthreads();
    constexpr int HALF = MT / 2;
    for (int o = tid; o < NT * HALF; o += 256) {
        int row = o / HALF, cp = o - row * HALF;
        uint32_t v = *(const uint32_t*)&ob[row * OSTR + cp * 2];
        *(uint32_t*)&out[(size_t)(tileP + row) * Cout + coutBase + cp * 2] = v;
    }
}

// ================= pool: NHWC bf16 -> NCHW fp32 (+ optional NHWC bf16) ========
__global__ __launch_bounds__(256) void k_poolT(
    const __nv_bfloat16* __restrict__ in, float* __restrict__ outN,
    __nv_bfloat16* __restrict__ outT, int C, int Ho, int Wo) {
    __shared__ float s[32][65];
    const int tid = threadIdx.x;
    const int p0 = blockIdx.x * 32;
    const int c0 = blockIdx.y * 64;
    const int b = blockIdx.z;
    const int W = Wo * 2;
    const __nv_bfloat16* inb = in + (size_t)b * (Ho * 2) * W * C;

    #pragma unroll
    for (int e = 0; e < 8; ++e) {
        int elem = tid + 256 * e;
        int c = elem & 63, pix = elem >> 6;
        int p = p0 + pix;
        int yy = p / Wo, xx = p - yy * Wo;
        const __nv_bfloat16* q = inb + ((size_t)(2 * yy) * W + 2 * xx) * C + c0 + c;
        float v0 = __bfloat162float(q[0]);
        float v1 = __bfloat162float(q[C]);
        float v2 = __bfloat162float(q[(size_t)W * C]);
        float v3 = __bfloat162float(q[(size_t)W * C + C]);
        float m = fmaxf(fmaxf(v0, v1), fmaxf(v2, v3));
        s[pix][c] = m;
        if (outT)
            outT[((size_t)b * Ho * Wo + p) * C + c0 + c] = __float2bfloat16(m);
    }
    __syncthreads();
    #pragma unroll
    for (int e = 0; e < 8; ++e) {
        int elem = tid + 256 * e;
        int pix = elem & 31, c = elem >> 5;
        outN[((size_t)(b * C + c0 + c)) * Ho * Wo + p0 + pix] = s[pix][c];
    }
}

// ================= tensor-core style Gram kernel =============================
__global__ __launch_bounds__(256) void k_gram_mma(
    const float* __restrict__ g, const float* __restrict__ a0,
    const float* __restrict__ a1, int Wd, int nT, double scale) {
    __shared__ __align__(16) __nv_bfloat16 sT[3][2][64][24];
    const int tid = threadIdx.x;
    const int lane = tid & 31, wid = tid >> 5;
    const int warpM = wid & 3, warpN = wid >> 2;

    int p = blockIdx.x, it = 0;
    while (p >= nT - it) { p -= nT - it; ++it; }
    const int jt = it + p;
    const int w0 = it * 64, v0 = jt * 64;

    const size_t base = (size_t)blockIdx.y * Wd * Wd;
    const float* mats[3] = {g, a0, a1};

    float acc[3][4][4];
    #pragma unroll
    for (int m = 0; m < 3; ++m)
        #pragma unroll
        for (int nj = 0; nj < 4; ++nj)
            #pragma unroll
            for (int e = 0; e < 4; ++e) acc[m][nj][e] = 0.f;

    const int nChunks = Wd >> 4;
    for (int kb = 0; kb < nChunks; ++kb) {
        __syncthreads();
        for (int o = tid; o < 6144; o += 256) {
            int mat = o / 2048;
            int r = o - mat * 2048;
            int sl = r >> 10;
            int e = r & 1023;
            int h = e >> 6, w = e & 63;
            int col0 = sl ? v0 : w0;
            float f = mats[mat][base + (size_t)(kb * 16 + h) * Wd + col0 + w];
            sT[mat][sl][w][h] = __float2bfloat16(f);
        }
        __syncthreads();

        #pragma unroll
        for (int mat = 0; mat < 3; ++mat) {
            uint32_t af[4];
            {
                int row = warpM * 16 + (lane & 7) + ((lane >> 3) & 1) * 8;
                int col = (lane >> 4) * 8;
                ldsm4(af[0], af[1], af[2], af[3], s2u(&sT[mat][0][row][col]));
            }
            uint32_t bf[4][2];
            #pragma unroll
            for (int pj = 0; pj < 2; ++pj) {
                int row = warpN * 32 + pj * 16 + (lane & 7) + (lane >> 4) * 8;
                int col = ((lane >> 3) & 1) * 8;
                uint32_t r0, r1, r2, r3;
                ldsm4(r0, r1, r2, r3, s2u(&sT[mat][1][row][col]));
                bf[2 * pj][0] = r0; bf[2 * pj][1] = r1;
                bf[2 * pj + 1][0] = r2; bf[2 * pj + 1][1] = r3;
            }
            #pragma unroll
            for (int nj = 0; nj < 4; ++nj)
                mma16816(acc[mat][nj], af, bf[nj]);
        }
    }

    float sum = 0.f;
    #pragma unroll
    for (int nj = 0; nj < 4; ++nj) {
        #pragma unroll
        for (int e = 0; e < 4; ++e) {
            int w = w0 + warpM * 16 + (lane >> 2) + (e >= 2 ? 8 : 0);
            int v = v0 + warpN * 32 + nj * 8 + (lane & 3) * 2 + (e & 1);
            float wgt = (jt > it) ? 2.f : (v > w ? 2.f : (v == w ? 1.f : 0.f));
            float gg = acc[0][nj][e];
            sum += wgt * (fabsf(acc[1][nj][e] - gg) + fabsf(acc[2][nj][e] - gg));
        }
    }
    block_reduce_add(sum, scale);
}

// ================= host orchestration =================
static const size_t g_wo[6] = {0, 36864, 110592, 258048, 552960, 1142784};

// remaining pipeline for one image AFTER conv0+l1 (which the caller launches)
static void run_tail(cudaStream_t st, int img, __nv_bfloat16* tA, __nv_bfloat16* tB,
                     __nv_bfloat16* wtb, const float* const* Bi,
                     float* p1, float* p2, float* p3,
                     size_t s1, size_t s2, size_t s3, int SM2) {
    k_poolT<<<dim3(2048, 1, 2), 256, 0, st>>>(tB, p1 + img * s1, tA, 64, 256, 256);
    k_convmma<128, 128><<<dim3(1024, 1), 256, SM2, st>>>(tA, tB, wtb + g_wo[1], Bi[2],
                                                         64, 128, 256, 256);
    k_convmma<128, 128><<<dim3(1024, 1), 256, SM2, st>>>(tB, tA, wtb + g_wo[2], Bi[3],
                                                         128, 128, 256, 256);
    k_poolT<<<dim3(512, 2, 2), 256, 0, st>>>(tA, p2 + img * s2, tB, 128, 128, 128);
    k_convmma<128, 128><<<dim3(256, 2), 256, SM2, st>>>(tB, tA, wtb + g_wo[3], Bi[4],
                                                        128, 256, 128, 128);
    k_convmma<128, 128><<<dim3(256, 2), 256, SM2, st>>>(tA, tB, wtb + g_wo[4], Bi[5],
                                                        256, 256, 128, 128);
    k_convmma<128, 128><<<dim3(256, 2), 256, SM2, st>>>(tB, tA, wtb + g_wo[5], Bi[6],
                                                        256, 256, 128, 128);
    k_poolT<<<dim3(128, 4, 2), 256, 0, st>>>(tA, p3 + img * s3, (__nv_bfloat16*)nullptr,
                                             256, 64, 64);
}

extern "C" void kernel_launch(void* const* d_in, const int* in_sizes, int n_in,
                              void* d_out, int out_size) {
    const float* igt  = (const float*)d_in[0];
    const float* iout = (const float*)d_in[1];
    const float* mask = (const float*)d_in[2];
    const float* W[7];
    const float* Bi[7];
    for (int i = 0; i < 7; ++i) {
        W[i]  = (const float*)d_in[3 + 2 * i];
        Bi[i] = (const float*)d_in[4 + 2 * i];
    }

    __nv_bfloat16 *tA0, *tB0, *wtb;
    float *comp, *p1, *p2, *p3;
    cudaGetSymbolAddress((void**)&tA0, d_tA);
    cudaGetSymbolAddress((void**)&tB0, d_tB);
    cudaGetSymbolAddress((void**)&wtb, d_wtb);
    cudaGetSymbolAddress((void**)&comp, d_compbuf);
    cudaGetSymbolAddress((void**)&p1, d_p1);
    cudaGetSymbolAddress((void**)&p2, d_p2);
    cudaGetSymbolAddress((void**)&p3, d_p3);
    __nv_bfloat16* tA[3] = {tA0, tA0 + 33554432, tA0 + 2 * 33554432};
    __nv_bfloat16* tB[3] = {tB0, tB0 + 33554432, tB0 + 2 * 33554432};

    const size_t s1 = 2ull * 64 * 256 * 256;
    const size_t s2 = 2ull * 128 * 128 * 128;
    const size_t s3 = 2ull * 256 * 64 * 64;

    const int SM1 = (3 * 64 + 256 + 2) * 72 * 2;    // 64800
    const int SM2 = (3 * 128 + 128 + 2) * 72 * 2;   // 74016
    cudaFuncSetAttribute(k_convmma<64, 256>,
                         cudaFuncAttributeMaxDynamicSharedMemorySize, SM1);
    cudaFuncSetAttribute(k_convmma<128, 128>,
                         cudaFuncAttributeMaxDynamicSharedMemorySize, SM2);

    // lazily-created side streams + fork/join events (host objects only)
    static cudaStream_t st1 = nullptr, st2 = nullptr;
    static cudaEvent_t eF = nullptr, eJ1 = nullptr, eJ2 = nullptr;
    if (!st1) {
        cudaStreamCreateWithFlags(&st1, cudaStreamNonBlocking);
        cudaStreamCreateWithFlags(&st2, cudaStreamNonBlocking);
        cudaEventCreateWithFlags(&eF, cudaEventDisableTiming);
        cudaEventCreateWithFlags(&eJ1, cudaEventDisableTiming);
        cudaEventCreateWithFlags(&eJ2, cudaEventDisableTiming);
    }

    // ---- prologue on origin stream (launches 1-4; #4 = k_convmma l1 for ncu)
    k_zero<<<1, 1>>>();                                                       // 1
    k_wt_all<<<dim3(2304, 6), 256>>>(W[1], W[2], W[3], W[4], W[5], W[6], wtb); // 2
    k_conv0<<<dim3(16, 16, 16), dim3(32, 8)>>>(iout, tA[0], W[0], Bi[0]);      // 3
    k_convmma<64, 256><<<dim3(2048, 1), 256, SM1>>>(tA[0], tB[0], wtb, Bi[1],
                                                    64, 64, 512, 512);         // 4
    const int nC = 2 * 3 * 512 * 512;
    k_comp<<<(nC + 255) / 256, 256>>>(igt, iout, mask);                        // 5
    k_holevalid<<<1024, 256>>>(igt, iout, mask);                               // 6

    // ---- fork: img1 (igt) on st1, img2 (comp) on st2
    cudaEventRecord(eF, 0);
    cudaStreamWaitEvent(st1, eF, 0);
    cudaStreamWaitEvent(st2, eF, 0);

    k_conv0<<<dim3(16, 16, 16), dim3(32, 8), 0, st1>>>(igt, tA[1], W[0], Bi[0]);
    k_convmma<64, 256><<<dim3(2048, 1), 256, SM1, st1>>>(tA[1], tB[1], wtb, Bi[1],
                                                         64, 64, 512, 512);
    run_tail(st1, 1, tA[1], tB[1], wtb, Bi, p1, p2, p3, s1, s2, s3, SM2);

    k_conv0<<<dim3(16, 16, 16), dim3(32, 8), 0, st2>>>(comp, tA[2], W[0], Bi[0]);
    k_convmma<64, 256><<<dim3(2048, 1), 256, SM1, st2>>>(tA[2], tB[2], wtb, Bi[1],
                                                         64, 64, 512, 512);
    run_tail(st2, 2, tA[2], tB[2], wtb, Bi, p1, p2, p3, s1, s2, s3, SM2);

    // ---- img0 tail continues on origin stream (concurrent with st1/st2)
    run_tail(0, 0, tA[0], tB[0], wtb, Bi, p1, p2, p3, s1, s2, s3, SM2);

    // ---- join
    cudaEventRecord(eJ1, st1);
    cudaEventRecord(eJ2, st2);
    cudaStreamWaitEvent(0, eJ1, 0);
    cudaStreamWaitEvent(0, eJ2, 0);

    // ---- reductions on origin stream
    const double invNigt = 1.0 / 8388608.0;
    k_perc<<<1024, 256>>>(p1, p1 + s1, p1 + 2 * s1, (int)s1, invNigt);
    k_perc<<<1024, 256>>>(p2, p2 + s2, p2 + 2 * s2, (int)s2, invNigt);
    k_perc<<<1024, 256>>>(p3, p3 + s3, p3 + 2 * s3, (int)s3, invNigt);

    {
        double sc = 1.0 / (64.0 * 256.0 * 256.0) / (64.0 * 64.0);
        k_gram_mma<<<dim3(10, 2 * 64), 256>>>(p1 + s1, p1, p1 + 2 * s1, 256, 4, sc);
    }
    {
        double sc = 1.0 / (128.0 * 128.0 * 128.0) / (128.0 * 128.0);
        k_gram_mma<<<dim3(3, 2 * 128), 256>>>(p2 + s2, p2, p2 + 2 * s2, 128, 2, sc);
    }
    {
        double sc = 1.0 / (256.0 * 64.0 * 64.0) / (256.0 * 256.0);
        k_gram_mma<<<dim3(1, 2 * 256), 256>>>(p3 + s3, p3, p3 + 2 * s3, 64, 1, sc);
    }

    k_final<<<1, 1>>>((float*)d_out);
}